// round 14
// baseline (speedup 1.0000x reference)
#include <cuda_runtime.h>
#include <cuda_bf16.h>
#include <cstdint>
#include <math.h>

#define B_WIN   3136
#define NTOK    64
#define DIM     256
#define HEADS   8
#define NW      49
#define LBIAS   225
#define ATT_SCALE 0.17677669529663687f  // 1/sqrt(32)
#define LOG2E   1.4426950408889634f
#define ATT_SCALE_L2E (0.17677669529663687f * 1.4426950408889634f)

// ---------------------------------------------------------------------------
// Plane layout (see R7): per (tile128, kchunk32) chunk, 2048 uint32 pairs.
// ---------------------------------------------------------------------------
__device__ uint32_t g_xhi [25690112];
__device__ uint32_t g_xlo [25690112];
__device__ uint32_t g_othi[25690112];
__device__ uint32_t g_otlo[25690112];
__device__ uint32_t g_wqh [98304];
__device__ uint32_t g_wql [98304];
__device__ uint32_t g_wph [32768];
__device__ uint32_t g_wpl [32768];
__device__ uint2    g_q2  [25690112];  // [B_*H][64][16] packed hi/lo (log2e-scaled)
__device__ uint2    g_k2  [25690112];
__device__ uint32_t g_vh  [25690112];  // v hi plane: [B_*H][64][16] bf16x2
__device__ uint32_t g_vl  [25690112];  // v lo plane
__device__ float    g_ptab[LBIAS * HEADS];
__device__ float    g_bm  [1605632];   // (bias+mask)*log2e  [49][8][64][64]

// ---------------------------------------------------------------------------
__device__ __forceinline__ void split2(float x, float y, uint32_t& hi, uint32_t& lo) {
    __nv_bfloat162 h = __floats2bfloat162_rn(x, y);
    float hx = __low2float(h), hy = __high2float(h);
    __nv_bfloat162 l = __floats2bfloat162_rn(x - hx, y - hy);
    hi = *reinterpret_cast<uint32_t*>(&h);
    lo = *reinterpret_cast<uint32_t*>(&l);
}

__device__ __forceinline__ uint32_t plane_pair(int r, int q) {
    int j = r >> 1;
    int u = (((r & 1) << 2) | (q >> 2)) ^ (j & 7);
    return (uint32_t)(j * 32 + u * 4 + (q & 3));
}

__device__ __forceinline__ void mma_bf16(float* c, const uint32_t* a, uint32_t b0, uint32_t b1) {
    asm volatile(
        "mma.sync.aligned.m16n8k16.row.col.f32.bf16.bf16.f32 "
        "{%0,%1,%2,%3}, {%4,%5,%6,%7}, {%8,%9}, {%0,%1,%2,%3};\n"
        : "+f"(c[0]), "+f"(c[1]), "+f"(c[2]), "+f"(c[3])
        : "r"(a[0]), "r"(a[1]), "r"(a[2]), "r"(a[3]), "r"(b0), "r"(b1));
}

__device__ __forceinline__ void ldsm4(uint32_t* r, uint32_t a) {
    asm volatile("ldmatrix.sync.aligned.m8n8.x4.shared.b16 {%0,%1,%2,%3}, [%4];"
                 : "=r"(r[0]), "=r"(r[1]), "=r"(r[2]), "=r"(r[3]) : "r"(a));
}

__device__ __forceinline__ void ldsm4t(uint32_t* r, uint32_t a) {
    asm volatile("ldmatrix.sync.aligned.m8n8.x4.trans.shared.b16 {%0,%1,%2,%3}, [%4];"
                 : "=r"(r[0]), "=r"(r[1]), "=r"(r[2]), "=r"(r[3]) : "r"(a));
}

__device__ __forceinline__ void ldgsts16(uint32_t saddr, const void* gp) {
    asm volatile("cp.async.cg.shared.global [%0], [%1], 16;\n" :: "r"(saddr), "l"(gp));
}

__device__ __forceinline__ float ex2(float x) {
    float y;
    asm("ex2.approx.f32 %0, %1;" : "=f"(y) : "f"(x));
    return y;
}

// ---------------------------------------------------------------------------
// Kernel 1: DynamicPosBias MLP -> g_ptab[225][8]
// ---------------------------------------------------------------------------
__device__ __forceinline__ void lnrelu16(const float* p, float* t,
                                         const float* gm, const float* bt) {
    float m = 0.f;
#pragma unroll
    for (int j = 0; j < 16; j++) m += p[j];
    m *= (1.f / 16.f);
    float v = 0.f;
#pragma unroll
    for (int j = 0; j < 16; j++) { float d = p[j] - m; v += d * d; }
    v *= (1.f / 16.f);
    float is = rsqrtf(v + 1e-5f);
#pragma unroll
    for (int j = 0; j < 16; j++) {
        float u = (p[j] - m) * is * gm[j] + bt[j];
        t[j] = u > 0.f ? u : 0.f;
    }
}

__global__ void dpb_kernel(const float* __restrict__ biases,
                           const float* __restrict__ pw, const float* __restrict__ pb,
                           const float* __restrict__ g1, const float* __restrict__ b1,
                           const float* __restrict__ w1, const float* __restrict__ c1,
                           const float* __restrict__ g2, const float* __restrict__ b2,
                           const float* __restrict__ w2, const float* __restrict__ c2,
                           const float* __restrict__ g3, const float* __restrict__ b3,
                           const float* __restrict__ w3, const float* __restrict__ c3) {
    int r = threadIdx.x;
    if (r >= LBIAS) return;
    float p[16], t[16];
    float x0 = biases[2 * r], x1 = biases[2 * r + 1];
#pragma unroll
    for (int j = 0; j < 16; j++) p[j] = x0 * pw[2 * j] + x1 * pw[2 * j + 1] + pb[j];
    lnrelu16(p, t, g1, b1);
#pragma unroll
    for (int o = 0; o < 16; o++) {
        float s = c1[o];
#pragma unroll
        for (int j = 0; j < 16; j++) s += t[j] * w1[o * 16 + j];
        p[o] = s;
    }
    lnrelu16(p, t, g2, b2);
#pragma unroll
    for (int o = 0; o < 16; o++) {
        float s = c2[o];
#pragma unroll
        for (int j = 0; j < 16; j++) s += t[j] * w2[o * 16 + j];
        p[o] = s;
    }
    lnrelu16(p, t, g3, b3);
#pragma unroll
    for (int o = 0; o < 8; o++) {
        float s = c3[o];
#pragma unroll
        for (int j = 0; j < 16; j++) s += t[j] * w3[o * 16 + j];
        g_ptab[r * 8 + o] = s;
    }
}

// ---------------------------------------------------------------------------
// Kernel 1b: pre-split x / qkv_w / proj_w into plane chunks (float4/thread)
// ---------------------------------------------------------------------------
__global__ void presplit_kernel(const float* __restrict__ x,
                                const float* __restrict__ qw,
                                const float* __restrict__ pw) {
    long i = (long)blockIdx.x * 256 + threadIdx.x;  // handles pairs 2i, 2i+1
    const float4* src; uint32_t *dh, *dl; long j2;
    if (i < 12845056L) { j2 = 2 * i; src = (const float4*)x; dh = g_xhi; dl = g_xlo; }
    else if (i < 12845056L + 49152) { j2 = 2 * (i - 12845056L); src = (const float4*)qw; dh = g_wqh; dl = g_wql; }
    else if (i < 12845056L + 49152 + 16384) { j2 = 2 * (i - 12845056L - 49152); src = (const float4*)pw; dh = g_wph; dl = g_wpl; }
    else return;
    float4 f = src[j2 >> 1];
    int m = (int)(j2 >> 7);
    int pc = (int)(j2 & 127);           // even
    int tile = m >> 7, r = m & 127;
    int kb = pc >> 4, q = pc & 15;      // q even -> idx, idx+1 consecutive
    long idx = ((long)(tile * 8 + kb)) * 2048 + plane_pair(r, q);
    uint32_t h0, l0, h1, l1;
    split2(f.x, f.y, h0, l0);
    split2(f.z, f.w, h1, l1);
    *(uint2*)(dh + idx) = make_uint2(h0, h1);
    *(uint2*)(dl + idx) = make_uint2(l0, l1);
}

// ---------------------------------------------------------------------------
// Kernel 1c: combined (bias+mask)*log2e table
// ---------------------------------------------------------------------------
__global__ void bmtab_kernel(const float* __restrict__ mask,
                             const int* __restrict__ rel_idx) {
    int wb = blockIdx.x, h = blockIdx.y;
    float* dst = g_bm + (size_t)(wb * 8 + h) * 4096;
    const float* msk = mask + (size_t)wb * 4096;
    for (int i = threadIdx.x; i < 4096; i += blockDim.x)
        dst[i] = (g_ptab[rel_idx[i] * 8 + h] + msk[i]) * LOG2E;
}

// ---------------------------------------------------------------------------
// Kernel 2/4: HMMA GEMM (75%-tensor mainloop, cp.async refill issued right
// after the barrier so it overlaps the mma work).
// ---------------------------------------------------------------------------
template <int MODE>
__global__ __launch_bounds__(256, 2) void gemm_kernel(const float* __restrict__ bias,
                                                      float* __restrict__ Out) {
    extern __shared__ char smem[];
    uint32_t sb = (uint32_t)__cvta_generic_to_shared(smem);

    int bm = blockIdx.y, bn = blockIdx.x;
    int tid = threadIdx.x;
    int warp = tid >> 5, lane = tid & 31;
    int wm = warp >> 1, wn = warp & 1;
    int g = lane >> 2, tg = lane & 3;

    const uint32_t* Ah = MODE ? g_othi : g_xhi;
    const uint32_t* Al = MODE ? g_otlo : g_xlo;
    const uint32_t* Bh = MODE ? g_wph : g_wqh;
    const uint32_t* Bl = MODE ? g_wpl : g_wql;

    float acc[2][8][4];
#pragma unroll
    for (int a = 0; a < 2; a++)
#pragma unroll
        for (int b = 0; b < 8; b++)
#pragma unroll
            for (int c = 0; c < 4; c++) acc[a][b][c] = 0.f;

    auto mkbase = [&](int r, int lb) {
        int j = r >> 1, a = (r & 1) << 2;
        return (uint32_t)(j * 128 + (((a ^ lb) ^ (j & 7)) << 4));
    };
    int rA = lane & 15, lbA = lane >> 4;
    uint32_t baseA0 = mkbase(wm * 32 + rA, lbA);
    uint32_t baseA1 = mkbase(wm * 32 + 16 + rA, lbA);
    int rB = (lane & 7) | ((lane >> 1) & 8);
    int lbB = (lane >> 3) & 1;
    uint32_t baseB[4];
#pragma unroll
    for (int i = 0; i < 4; i++) baseB[i] = mkbase(wn * 64 + i * 16 + rB, lbB);

    auto issue = [&](int kb, int s) {
        uint32_t S = sb + (uint32_t)s * 32768;
        const uint32_t* srcs[4] = {
            Ah + (size_t)(bm * 8 + kb) * 2048, Al + (size_t)(bm * 8 + kb) * 2048,
            Bh + (size_t)(bn * 8 + kb) * 2048, Bl + (size_t)(bn * 8 + kb) * 2048 };
#pragma unroll
        for (int p = 0; p < 4; p++) {
#pragma unroll
            for (int e = 0; e < 2; e++) {
                int u = tid + e * 256;
                ldgsts16(S + (uint32_t)p * 8192 + u * 16, srcs[p] + u * 4);
            }
        }
        asm volatile("cp.async.commit_group;\n" ::: "memory");
    };

    issue(0, 0);
    issue(1, 1);

    for (int kb = 0; kb < 8; kb++) {
        int s = kb % 3;
        if (kb < 7) asm volatile("cp.async.wait_group 1;\n" ::: "memory");
        else        asm volatile("cp.async.wait_group 0;\n" ::: "memory");
        __syncthreads();
        // stage (kb+2)%3 was last read in iteration kb-1; the barrier above
        // proves all warps finished it -> refill now, overlapping the mma.
        if (kb < 6) issue(kb + 2, (kb + 2) % 3);

        uint32_t S = sb + (uint32_t)s * 32768;
#pragma unroll
        for (int ks = 0; ks < 2; ks++) {
            uint32_t uo = ks * 32;
            uint32_t ah0[4], ah1[4], al0[4], al1[4];
            ldsm4(ah0, S + (baseA0 ^ uo));
            ldsm4(ah1, S + (baseA1 ^ uo));
            ldsm4(al0, S + 8192 + (baseA0 ^ uo));
            ldsm4(al1, S + 8192 + (baseA1 ^ uo));
#pragma unroll
            for (int nfp = 0; nfp < 4; nfp++) {
                int nf0 = 2 * nfp, nf1 = nf0 + 1;
                uint32_t bh[4], bl[4];
                ldsm4(bh, S + 16384 + (baseB[nfp] ^ uo));
                ldsm4(bl, S + 24576 + (baseB[nfp] ^ uo));
                mma_bf16(acc[0][nf0], ah0, bh[0], bh[1]);
                mma_bf16(acc[1][nf0], ah1, bh[0], bh[1]);
                mma_bf16(acc[0][nf1], ah0, bh[2], bh[3]);
                mma_bf16(acc[1][nf1], ah1, bh[2], bh[3]);
                mma_bf16(acc[0][nf0], ah0, bl[0], bl[1]);
                mma_bf16(acc[1][nf0], ah1, bl[0], bl[1]);
                mma_bf16(acc[0][nf1], ah0, bl[2], bl[3]);
                mma_bf16(acc[1][nf1], ah1, bl[2], bl[3]);
                mma_bf16(acc[0][nf0], al0, bh[0], bh[1]);
                mma_bf16(acc[1][nf0], al1, bh[0], bh[1]);
                mma_bf16(acc[0][nf1], al0, bh[2], bh[3]);
                mma_bf16(acc[1][nf1], al1, bh[2], bh[3]);
            }
        }
    }

    int obase = bn * 128 + wn * 64;
#pragma unroll
    for (int nf = 0; nf < 8; nf++) {
        int o = obase + nf * 8 + 2 * tg;
        float bb0 = bias[o], bb1 = bias[o + 1];
#pragma unroll
        for (int mf = 0; mf < 2; mf++) {
#pragma unroll
            for (int r2 = 0; r2 < 2; r2++) {
                int m = bm * 128 + wm * 32 + mf * 16 + g + r2 * 8;
                float v0 = acc[mf][nf][r2 * 2] + bb0;
                float v1 = acc[mf][nf][r2 * 2 + 1] + bb1;
                if (MODE == 1) {
                    *(float2*)(Out + (size_t)m * 256 + o) = make_float2(v0, v1);
                } else {
                    int s = o >> 8, hh = (o >> 5) & 7, d = o & 31;
                    int bw = m >> 6, n = m & 63;
                    size_t di = ((size_t)(bw * 8 + hh) * 64 + n) * 16 + (d >> 1);
                    uint32_t hi, lo;
                    if (s == 0)      { uint2 u; split2(v0 * ATT_SCALE_L2E, v1 * ATT_SCALE_L2E, u.x, u.y); g_q2[di] = u; }
                    else if (s == 1) { uint2 u; split2(v0, v1, u.x, u.y); g_k2[di] = u; }
                    else             { split2(v0, v1, hi, lo); g_vh[di] = hi; g_vl[di] = lo; }
                }
            }
        }
    }
}

// ---------------------------------------------------------------------------
// Kernel 3: attention. Grid transposed to (HEADS, B_WIN) so adjacent blocks
// stream contiguous q/k/v spans. Deferred softmax normalization.
// ---------------------------------------------------------------------------
__global__ __launch_bounds__(128, 6) void attn_kernel() {
    __shared__ uint2    k2s[64][20];
    __shared__ uint32_t vhs[64][20];
    __shared__ uint32_t vls[64][20];
    __shared__ float    bms[64][68];

    int b = blockIdx.y, h = blockIdx.x;
    int tid = threadIdx.x;
    int warp = tid >> 5, lane = tid & 31;
    int g = lane >> 2, tg = lane & 3;
    int mr = warp * 16;

    const uint2*    qg = g_q2 + (size_t)(b * 8 + h) * 1024;
    const uint2*    kg = g_k2 + (size_t)(b * 8 + h) * 1024;
    const uint32_t* vhg = g_vh + (size_t)(b * 8 + h) * 1024;
    const uint32_t* vlg = g_vl + (size_t)(b * 8 + h) * 1024;
    const float*    bmr = g_bm + (size_t)((b % NW) * 8 + h) * 4096;

#pragma unroll
    for (int e = 0; e < 4; e++) {
        int it = tid + e * 128;
        int t = it >> 3, j = (it & 7) * 2;
        ldgsts16((uint32_t)__cvta_generic_to_shared(&k2s[t][j]), kg + t * 16 + j);
    }
    asm volatile("cp.async.commit_group;\n" ::: "memory");

    uint32_t vhb = (uint32_t)__cvta_generic_to_shared(&vhs[0][0]);
    uint32_t vlb = (uint32_t)__cvta_generic_to_shared(&vls[0][0]);
#pragma unroll
    for (int e = 0; e < 2; e++) {
        int u = tid + e * 128;
        int t = u >> 2, part = u & 3;
        ldgsts16(vhb + (uint32_t)(t * 80 + part * 16), vhg + t * 16 + part * 4);
        ldgsts16(vlb + (uint32_t)(t * 80 + part * 16), vlg + t * 16 + part * 4);
    }
    asm volatile("cp.async.commit_group;\n" ::: "memory");

    uint32_t bmsb = (uint32_t)__cvta_generic_to_shared(&bms[0][0]);
#pragma unroll
    for (int e = 0; e < 8; e++) {
        int i = lane + 32 * e;
        int rr = warp * 16 + (i >> 4);
        int cu = (i & 15) * 4;
        ldgsts16(bmsb + (uint32_t)(rr * 68 + cu) * 4, bmr + rr * 64 + cu);
    }
    asm volatile("cp.async.commit_group;\n" ::: "memory");

    uint32_t qh_[2][4], ql_[2][4];
#pragma unroll
    for (int ks = 0; ks < 2; ks++) {
        int j0 = ks * 8;
        uint2 t;
        t = qg[(mr + g) * 16 + j0 + tg];          qh_[ks][0] = t.x; ql_[ks][0] = t.y;
        t = qg[(mr + g + 8) * 16 + j0 + tg];      qh_[ks][1] = t.x; ql_[ks][1] = t.y;
        t = qg[(mr + g) * 16 + j0 + tg + 4];      qh_[ks][2] = t.x; ql_[ks][2] = t.y;
        t = qg[(mr + g + 8) * 16 + j0 + tg + 4];  qh_[ks][3] = t.x; ql_[ks][3] = t.y;
    }

    asm volatile("cp.async.wait_group 2;\n" ::: "memory");
    __syncthreads();

    float acc[8][4];
#pragma unroll
    for (int a = 0; a < 8; a++)
#pragma unroll
        for (int c = 0; c < 4; c++) acc[a][c] = 0.f;

#pragma unroll
    for (int ks = 0; ks < 2; ks++) {
        int j0 = ks * 8;
#pragma unroll
        for (int nfp = 0; nfp < 4; nfp++) {
            int nf0 = 2 * nfp, nf1 = nf0 + 1;
            int n0 = nf0 * 8 + g;
            uint2 c0 = k2s[n0][j0 + tg],     c1 = k2s[n0][j0 + tg + 4];
            uint2 d0 = k2s[n0 + 8][j0 + tg], d1 = k2s[n0 + 8][j0 + tg + 4];
            mma_bf16(acc[nf0], qh_[ks], c0.x, c1.x);
            mma_bf16(acc[nf1], qh_[ks], d0.x, d1.x);
            mma_bf16(acc[nf0], qh_[ks], c0.y, c1.y);
            mma_bf16(acc[nf1], qh_[ks], d0.y, d1.y);
            mma_bf16(acc[nf0], ql_[ks], c0.x, c1.x);
            mma_bf16(acc[nf1], ql_[ks], d0.x, d1.x);
        }
    }

    asm volatile("cp.async.wait_group 0;\n" ::: "memory");
    __syncthreads();

    int r0 = mr + g, r1 = r0 + 8;
#pragma unroll
    for (int nf = 0; nf < 8; nf++) {
        int n0 = nf * 8 + 2 * tg;
        float2 e0 = *(const float2*)(&bms[r0][n0]);
        float2 e1 = *(const float2*)(&bms[r1][n0]);
        acc[nf][0] += e0.x; acc[nf][1] += e0.y;
        acc[nf][2] += e1.x; acc[nf][3] += e1.y;
    }

    float m0 = -1e30f, m1 = -1e30f;
#pragma unroll
    for (int nf = 0; nf < 8; nf++) {
        m0 = fmaxf(m0, fmaxf(acc[nf][0], acc[nf][1]));
        m1 = fmaxf(m1, fmaxf(acc[nf][2], acc[nf][3]));
    }
    m0 = fmaxf(m0, __shfl_xor_sync(0xffffffffu, m0, 1));
    m0 = fmaxf(m0, __shfl_xor_sync(0xffffffffu, m0, 2));
    m1 = fmaxf(m1, __shfl_xor_sync(0xffffffffu, m1, 1));
    m1 = fmaxf(m1, __shfl_xor_sync(0xffffffffu, m1, 2));

    // unnormalized probs; sums reduce in parallel with P.V below
    float s0 = 0.f, s1 = 0.f;
#pragma unroll
    for (int nf = 0; nf < 8; nf++) {
        acc[nf][0] = ex2(acc[nf][0] - m0); s0 += acc[nf][0];
        acc[nf][1] = ex2(acc[nf][1] - m0); s0 += acc[nf][1];
        acc[nf][2] = ex2(acc[nf][2] - m1); s1 += acc[nf][2];
        acc[nf][3] = ex2(acc[nf][3] - m1); s1 += acc[nf][3];
    }

    float oacc[4][4];
#pragma unroll
    for (int a = 0; a < 4; a++)
#pragma unroll
        for (int c = 0; c < 4; c++) oacc[a][c] = 0.f;

    uint32_t vrow = (uint32_t)(((lane >> 3) & 1) * 8 + (lane & 7));
    uint32_t vcol = (uint32_t)((lane >> 4) * 16);
    uint32_t vh_l = vhb + vrow * 80 + vcol;
    uint32_t vl_l = vlb + vrow * 80 + vcol;

#pragma unroll
    for (int ks = 0; ks < 4; ks++) {
        uint32_t ah[4], al[4];
        split2(acc[2 * ks][0],     acc[2 * ks][1],     ah[0], al[0]);
        split2(acc[2 * ks][2],     acc[2 * ks][3],     ah[1], al[1]);
        split2(acc[2 * ks + 1][0], acc[2 * ks + 1][1], ah[2], al[2]);
        split2(acc[2 * ks + 1][2], acc[2 * ks + 1][3], ah[3], al[3]);
        uint32_t ko = (uint32_t)(ks * 16 * 80);
        uint32_t bh0[4], bh1[4], bl0[4], bl1[4];
        ldsm4t(bh0, vh_l + ko);
        ldsm4t(bh1, vh_l + ko + 32);
        ldsm4t(bl0, vl_l + ko);
        ldsm4t(bl1, vl_l + ko + 32);
        mma_bf16(oacc[0], ah, bh0[0], bh0[1]);
        mma_bf16(oacc[1], ah, bh0[2], bh0[3]);
        mma_bf16(oacc[2], ah, bh1[0], bh1[1]);
        mma_bf16(oacc[3], ah, bh1[2], bh1[3]);
        mma_bf16(oacc[0], ah, bl0[0], bl0[1]);
        mma_bf16(oacc[1], ah, bl0[2], bl0[3]);
        mma_bf16(oacc[2], ah, bl1[0], bl1[1]);
        mma_bf16(oacc[3], ah, bl1[2], bl1[3]);
        mma_bf16(oacc[0], al, bh0[0], bh0[1]);
        mma_bf16(oacc[1], al, bh0[2], bh0[3]);
        mma_bf16(oacc[2], al, bh1[0], bh1[1]);
        mma_bf16(oacc[3], al, bh1[2], bh1[3]);
    }

    s0 += __shfl_xor_sync(0xffffffffu, s0, 1);
    s0 += __shfl_xor_sync(0xffffffffu, s0, 2);
    s1 += __shfl_xor_sync(0xffffffffu, s1, 1);
    s1 += __shfl_xor_sync(0xffffffffu, s1, 2);
    float i0 = 1.f / s0, i1 = 1.f / s1;

    int m0r = b * 64 + r0, m1r = b * 64 + r1;
#pragma unroll
    for (int nf = 0; nf < 4; nf++) {
        int dp = h * 16 + nf * 4 + tg;
        int kb = dp >> 4, q = dp & 15;
        uint32_t hi, lo;
        {
            size_t idx = ((size_t)((m0r >> 7) * 8 + kb)) * 2048 + plane_pair(m0r & 127, q);
            split2(oacc[nf][0] * i0, oacc[nf][1] * i0, hi, lo);
            g_othi[idx] = hi; g_otlo[idx] = lo;
        }
        {
            size_t idx = ((size_t)((m1r >> 7) * 8 + kb)) * 2048 + plane_pair(m1r & 127, q);
            split2(oacc[nf][2] * i1, oacc[nf][3] * i1, hi, lo);
            g_othi[idx] = hi; g_otlo[idx] = lo;
        }
    }
}

// ---------------------------------------------------------------------------
extern "C" void kernel_launch(void* const* d_in, const int* in_sizes, int n_in,
                              void* d_out, int out_size) {
    (void)in_sizes; (void)n_in; (void)out_size;
    const float* x       = (const float*)d_in[0];
    const float* mask    = (const float*)d_in[1];
    const float* qkv_w   = (const float*)d_in[2];
    const float* qkv_b   = (const float*)d_in[3];
    const float* proj_w  = (const float*)d_in[4];
    const float* proj_b  = (const float*)d_in[5];
    const float* pposw   = (const float*)d_in[6];
    const float* pposb   = (const float*)d_in[7];
    const float* ln1g    = (const float*)d_in[8];
    const float* ln1b    = (const float*)d_in[9];
    const float* fc1w    = (const float*)d_in[10];
    const float* fc1b    = (const float*)d_in[11];
    const float* ln2g    = (const float*)d_in[12];
    const float* ln2b    = (const float*)d_in[13];
    const float* fc2w    = (const float*)d_in[14];
    const float* fc2b    = (const float*)d_in[15];
    const float* ln3g    = (const float*)d_in[16];
    const float* ln3b    = (const float*)d_in[17];
    const float* fc3w    = (const float*)d_in[18];
    const float* fc3b    = (const float*)d_in[19];
    const float* biases  = (const float*)d_in[20];
    const int*   rel_idx = (const int*)d_in[21];
    float* out = (float*)d_out;

    static bool attr_set = false;
    if (!attr_set) {
        cudaFuncSetAttribute(gemm_kernel<0>, cudaFuncAttributeMaxDynamicSharedMemorySize, 98304);
        cudaFuncSetAttribute(gemm_kernel<1>, cudaFuncAttributeMaxDynamicSharedMemorySize, 98304);
        attr_set = true;
    }

    dpb_kernel<<<1, 256>>>(biases, pposw, pposb, ln1g, ln1b, fc1w, fc1b,
                           ln2g, ln2b, fc2w, fc2b, ln3g, ln3b, fc3w, fc3b);
    presplit_kernel<<<50432, 256>>>(x, qkv_w, proj_w);
    bmtab_kernel<<<dim3(NW, HEADS), 256>>>(mask, rel_idx);
    gemm_kernel<0><<<dim3(6, 1568), 256, 98304>>>(qkv_b, nullptr);
    attn_kernel<<<dim3(HEADS, B_WIN), 128>>>();
    gemm_kernel<1><<<dim3(2, 1568), 256, 98304>>>(proj_b, out);
}

// round 15
// speedup vs baseline: 1.0512x; 1.0512x over previous
#include <cuda_runtime.h>
#include <cuda_bf16.h>
#include <cstdint>
#include <math.h>

#define B_WIN   3136
#define NTOK    64
#define DIM     256
#define HEADS   8
#define NW      49
#define LBIAS   225
#define ATT_SCALE 0.17677669529663687f  // 1/sqrt(32)
#define LOG2E   1.4426950408889634f
#define ATT_SCALE_L2E (0.17677669529663687f * 1.4426950408889634f)

// ---------------------------------------------------------------------------
// Plane layout (see R7): per (tile128, kchunk32) chunk, 2048 uint32 pairs.
// ---------------------------------------------------------------------------
__device__ uint32_t g_xhi [25690112];
__device__ uint32_t g_xlo [25690112];
__device__ uint32_t g_othi[25690112];
__device__ uint32_t g_otlo[25690112];
__device__ uint32_t g_wqh [98304];
__device__ uint32_t g_wql [98304];
__device__ uint32_t g_wph [32768];
__device__ uint32_t g_wpl [32768];
__device__ uint32_t g_q1  [25690112];  // q hi-only bf16x2/pair (log2e-scaled)
__device__ uint32_t g_k1  [25690112];  // k hi-only
__device__ uint32_t g_vh  [25690112];  // v hi plane
__device__ uint32_t g_vl  [25690112];  // v lo plane
__device__ float    g_ptab[LBIAS * HEADS];
__device__ float    g_bm  [1605632];   // (bias+mask)*log2e  [49][8][64][64]

// ---------------------------------------------------------------------------
__device__ __forceinline__ void split2(float x, float y, uint32_t& hi, uint32_t& lo) {
    __nv_bfloat162 h = __floats2bfloat162_rn(x, y);
    float hx = __low2float(h), hy = __high2float(h);
    __nv_bfloat162 l = __floats2bfloat162_rn(x - hx, y - hy);
    hi = *reinterpret_cast<uint32_t*>(&h);
    lo = *reinterpret_cast<uint32_t*>(&l);
}

__device__ __forceinline__ uint32_t pack_hi(float x, float y) {
    __nv_bfloat162 h = __floats2bfloat162_rn(x, y);
    return *reinterpret_cast<uint32_t*>(&h);
}

__device__ __forceinline__ uint32_t plane_pair(int r, int q) {
    int j = r >> 1;
    int u = (((r & 1) << 2) | (q >> 2)) ^ (j & 7);
    return (uint32_t)(j * 32 + u * 4 + (q & 3));
}

__device__ __forceinline__ void mma_bf16(float* c, const uint32_t* a, uint32_t b0, uint32_t b1) {
    asm volatile(
        "mma.sync.aligned.m16n8k16.row.col.f32.bf16.bf16.f32 "
        "{%0,%1,%2,%3}, {%4,%5,%6,%7}, {%8,%9}, {%0,%1,%2,%3};\n"
        : "+f"(c[0]), "+f"(c[1]), "+f"(c[2]), "+f"(c[3])
        : "r"(a[0]), "r"(a[1]), "r"(a[2]), "r"(a[3]), "r"(b0), "r"(b1));
}

__device__ __forceinline__ void ldsm4(uint32_t* r, uint32_t a) {
    asm volatile("ldmatrix.sync.aligned.m8n8.x4.shared.b16 {%0,%1,%2,%3}, [%4];"
                 : "=r"(r[0]), "=r"(r[1]), "=r"(r[2]), "=r"(r[3]) : "r"(a));
}

__device__ __forceinline__ void ldsm4t(uint32_t* r, uint32_t a) {
    asm volatile("ldmatrix.sync.aligned.m8n8.x4.trans.shared.b16 {%0,%1,%2,%3}, [%4];"
                 : "=r"(r[0]), "=r"(r[1]), "=r"(r[2]), "=r"(r[3]) : "r"(a));
}

__device__ __forceinline__ void ldgsts16(uint32_t saddr, const void* gp) {
    asm volatile("cp.async.cg.shared.global [%0], [%1], 16;\n" :: "r"(saddr), "l"(gp));
}

__device__ __forceinline__ float ex2(float x) {
    float y;
    asm("ex2.approx.f32 %0, %1;" : "=f"(y) : "f"(x));
    return y;
}

// ---------------------------------------------------------------------------
// Kernel 1: DynamicPosBias MLP -> g_ptab[225][8]
// ---------------------------------------------------------------------------
__device__ __forceinline__ void lnrelu16(const float* p, float* t,
                                         const float* gm, const float* bt) {
    float m = 0.f;
#pragma unroll
    for (int j = 0; j < 16; j++) m += p[j];
    m *= (1.f / 16.f);
    float v = 0.f;
#pragma unroll
    for (int j = 0; j < 16; j++) { float d = p[j] - m; v += d * d; }
    v *= (1.f / 16.f);
    float is = rsqrtf(v + 1e-5f);
#pragma unroll
    for (int j = 0; j < 16; j++) {
        float u = (p[j] - m) * is * gm[j] + bt[j];
        t[j] = u > 0.f ? u : 0.f;
    }
}

__global__ void dpb_kernel(const float* __restrict__ biases,
                           const float* __restrict__ pw, const float* __restrict__ pb,
                           const float* __restrict__ g1, const float* __restrict__ b1,
                           const float* __restrict__ w1, const float* __restrict__ c1,
                           const float* __restrict__ g2, const float* __restrict__ b2,
                           const float* __restrict__ w2, const float* __restrict__ c2,
                           const float* __restrict__ g3, const float* __restrict__ b3,
                           const float* __restrict__ w3, const float* __restrict__ c3) {
    int r = threadIdx.x;
    if (r >= LBIAS) return;
    float p[16], t[16];
    float x0 = biases[2 * r], x1 = biases[2 * r + 1];
#pragma unroll
    for (int j = 0; j < 16; j++) p[j] = x0 * pw[2 * j] + x1 * pw[2 * j + 1] + pb[j];
    lnrelu16(p, t, g1, b1);
#pragma unroll
    for (int o = 0; o < 16; o++) {
        float s = c1[o];
#pragma unroll
        for (int j = 0; j < 16; j++) s += t[j] * w1[o * 16 + j];
        p[o] = s;
    }
    lnrelu16(p, t, g2, b2);
#pragma unroll
    for (int o = 0; o < 16; o++) {
        float s = c2[o];
#pragma unroll
        for (int j = 0; j < 16; j++) s += t[j] * w2[o * 16 + j];
        p[o] = s;
    }
    lnrelu16(p, t, g3, b3);
#pragma unroll
    for (int o = 0; o < 8; o++) {
        float s = c3[o];
#pragma unroll
        for (int j = 0; j < 16; j++) s += t[j] * w3[o * 16 + j];
        g_ptab[r * 8 + o] = s;
    }
}

// ---------------------------------------------------------------------------
// Kernel 1b: pre-split x / qkv_w / proj_w into plane chunks (float4/thread)
// ---------------------------------------------------------------------------
__global__ void presplit_kernel(const float* __restrict__ x,
                                const float* __restrict__ qw,
                                const float* __restrict__ pw) {
    long i = (long)blockIdx.x * 256 + threadIdx.x;  // handles pairs 2i, 2i+1
    const float4* src; uint32_t *dh, *dl; long j2;
    if (i < 12845056L) { j2 = 2 * i; src = (const float4*)x; dh = g_xhi; dl = g_xlo; }
    else if (i < 12845056L + 49152) { j2 = 2 * (i - 12845056L); src = (const float4*)qw; dh = g_wqh; dl = g_wql; }
    else if (i < 12845056L + 49152 + 16384) { j2 = 2 * (i - 12845056L - 49152); src = (const float4*)pw; dh = g_wph; dl = g_wpl; }
    else return;
    float4 f = src[j2 >> 1];
    int m = (int)(j2 >> 7);
    int pc = (int)(j2 & 127);           // even
    int tile = m >> 7, r = m & 127;
    int kb = pc >> 4, q = pc & 15;      // q even -> idx, idx+1 consecutive
    long idx = ((long)(tile * 8 + kb)) * 2048 + plane_pair(r, q);
    uint32_t h0, l0, h1, l1;
    split2(f.x, f.y, h0, l0);
    split2(f.z, f.w, h1, l1);
    *(uint2*)(dh + idx) = make_uint2(h0, h1);
    *(uint2*)(dl + idx) = make_uint2(l0, l1);
}

// ---------------------------------------------------------------------------
// Kernel 1c: combined (bias+mask)*log2e table
// ---------------------------------------------------------------------------
__global__ void bmtab_kernel(const float* __restrict__ mask,
                             const int* __restrict__ rel_idx) {
    int wb = blockIdx.x, h = blockIdx.y;
    float* dst = g_bm + (size_t)(wb * 8 + h) * 4096;
    const float* msk = mask + (size_t)wb * 4096;
    for (int i = threadIdx.x; i < 4096; i += blockDim.x)
        dst[i] = (g_ptab[rel_idx[i] * 8 + h] + msk[i]) * LOG2E;
}

// ---------------------------------------------------------------------------
// Kernel 2/4: HMMA GEMM (R13-exact mainloop: issue at loop end).
// ---------------------------------------------------------------------------
template <int MODE>
__global__ __launch_bounds__(256, 2) void gemm_kernel(const float* __restrict__ bias,
                                                      float* __restrict__ Out) {
    extern __shared__ char smem[];
    uint32_t sb = (uint32_t)__cvta_generic_to_shared(smem);

    int bm = blockIdx.y, bn = blockIdx.x;
    int tid = threadIdx.x;
    int warp = tid >> 5, lane = tid & 31;
    int wm = warp >> 1, wn = warp & 1;
    int g = lane >> 2, tg = lane & 3;

    const uint32_t* Ah = MODE ? g_othi : g_xhi;
    const uint32_t* Al = MODE ? g_otlo : g_xlo;
    const uint32_t* Bh = MODE ? g_wph : g_wqh;
    const uint32_t* Bl = MODE ? g_wpl : g_wql;

    float acc[2][8][4];
#pragma unroll
    for (int a = 0; a < 2; a++)
#pragma unroll
        for (int b = 0; b < 8; b++)
#pragma unroll
            for (int c = 0; c < 4; c++) acc[a][b][c] = 0.f;

    auto mkbase = [&](int r, int lb) {
        int j = r >> 1, a = (r & 1) << 2;
        return (uint32_t)(j * 128 + (((a ^ lb) ^ (j & 7)) << 4));
    };
    int rA = lane & 15, lbA = lane >> 4;
    uint32_t baseA0 = mkbase(wm * 32 + rA, lbA);
    uint32_t baseA1 = mkbase(wm * 32 + 16 + rA, lbA);
    int rB = (lane & 7) | ((lane >> 1) & 8);
    int lbB = (lane >> 3) & 1;
    uint32_t baseB[4];
#pragma unroll
    for (int i = 0; i < 4; i++) baseB[i] = mkbase(wn * 64 + i * 16 + rB, lbB);

    auto issue = [&](int kb, int s) {
        uint32_t S = sb + (uint32_t)s * 32768;
        const uint32_t* srcs[4] = {
            Ah + (size_t)(bm * 8 + kb) * 2048, Al + (size_t)(bm * 8 + kb) * 2048,
            Bh + (size_t)(bn * 8 + kb) * 2048, Bl + (size_t)(bn * 8 + kb) * 2048 };
#pragma unroll
        for (int p = 0; p < 4; p++) {
#pragma unroll
            for (int e = 0; e < 2; e++) {
                int u = tid + e * 256;
                ldgsts16(S + (uint32_t)p * 8192 + u * 16, srcs[p] + u * 4);
            }
        }
        asm volatile("cp.async.commit_group;\n" ::: "memory");
    };

    issue(0, 0);
    issue(1, 1);

    for (int kb = 0; kb < 8; kb++) {
        int s = kb % 3;
        if (kb < 7) asm volatile("cp.async.wait_group 1;\n" ::: "memory");
        else        asm volatile("cp.async.wait_group 0;\n" ::: "memory");
        __syncthreads();

        uint32_t S = sb + (uint32_t)s * 32768;
#pragma unroll
        for (int ks = 0; ks < 2; ks++) {
            uint32_t uo = ks * 32;
            uint32_t ah0[4], ah1[4], al0[4], al1[4];
            ldsm4(ah0, S + (baseA0 ^ uo));
            ldsm4(ah1, S + (baseA1 ^ uo));
            ldsm4(al0, S + 8192 + (baseA0 ^ uo));
            ldsm4(al1, S + 8192 + (baseA1 ^ uo));
#pragma unroll
            for (int nfp = 0; nfp < 4; nfp++) {
                int nf0 = 2 * nfp, nf1 = nf0 + 1;
                uint32_t bh[4], bl[4];
                ldsm4(bh, S + 16384 + (baseB[nfp] ^ uo));
                ldsm4(bl, S + 24576 + (baseB[nfp] ^ uo));
                mma_bf16(acc[0][nf0], ah0, bh[0], bh[1]);
                mma_bf16(acc[1][nf0], ah1, bh[0], bh[1]);
                mma_bf16(acc[0][nf1], ah0, bh[2], bh[3]);
                mma_bf16(acc[1][nf1], ah1, bh[2], bh[3]);
                mma_bf16(acc[0][nf0], ah0, bl[0], bl[1]);
                mma_bf16(acc[1][nf0], ah1, bl[0], bl[1]);
                mma_bf16(acc[0][nf1], ah0, bl[2], bl[3]);
                mma_bf16(acc[1][nf1], ah1, bl[2], bl[3]);
                mma_bf16(acc[0][nf0], al0, bh[0], bh[1]);
                mma_bf16(acc[1][nf0], al1, bh[0], bh[1]);
                mma_bf16(acc[0][nf1], al0, bh[2], bh[3]);
                mma_bf16(acc[1][nf1], al1, bh[2], bh[3]);
            }
        }
        if (kb < 6) issue(kb + 2, (kb + 2) % 3);
    }

    int obase = bn * 128 + wn * 64;
#pragma unroll
    for (int nf = 0; nf < 8; nf++) {
        int o = obase + nf * 8 + 2 * tg;
        float bb0 = bias[o], bb1 = bias[o + 1];
#pragma unroll
        for (int mf = 0; mf < 2; mf++) {
#pragma unroll
            for (int r2 = 0; r2 < 2; r2++) {
                int m = bm * 128 + wm * 32 + mf * 16 + g + r2 * 8;
                float v0 = acc[mf][nf][r2 * 2] + bb0;
                float v1 = acc[mf][nf][r2 * 2 + 1] + bb1;
                if (MODE == 1) {
                    *(float2*)(Out + (size_t)m * 256 + o) = make_float2(v0, v1);
                } else {
                    int s = o >> 8, hh = (o >> 5) & 7, d = o & 31;
                    int bw = m >> 6, n = m & 63;
                    size_t di = ((size_t)(bw * 8 + hh) * 64 + n) * 16 + (d >> 1);
                    uint32_t hi, lo;
                    if (s == 0)      { g_q1[di] = pack_hi(v0 * ATT_SCALE_L2E, v1 * ATT_SCALE_L2E); }
                    else if (s == 1) { g_k1[di] = pack_hi(v0, v1); }
                    else             { split2(v0, v1, hi, lo); g_vh[di] = hi; g_vl[di] = lo; }
                }
            }
        }
    }
}

// ---------------------------------------------------------------------------
// Kernel 3: attention per (window b, head h). q/k hi-only bf16 (QK^T single
// mma term); P.V stays bf16x3. Deferred normalization.
// ---------------------------------------------------------------------------
__global__ __launch_bounds__(128, 6) void attn_kernel() {
    __shared__ uint32_t k1s[64][20];  // k hi rows: 64B data + 16B pad
    __shared__ uint32_t vhs[64][20];
    __shared__ uint32_t vls[64][20];
    __shared__ float    bms[64][68];

    int b = blockIdx.x, h = blockIdx.y;
    int tid = threadIdx.x;
    int warp = tid >> 5, lane = tid & 31;
    int g = lane >> 2, tg = lane & 3;
    int mr = warp * 16;

    const uint32_t* qg = g_q1 + (size_t)(b * 8 + h) * 1024;
    const uint32_t* kg = g_k1 + (size_t)(b * 8 + h) * 1024;
    const uint32_t* vhg = g_vh + (size_t)(b * 8 + h) * 1024;
    const uint32_t* vlg = g_vl + (size_t)(b * 8 + h) * 1024;
    const float*    bmr = g_bm + (size_t)((b % NW) * 8 + h) * 4096;

    // group 0: k hi tile (256 16B units)
    uint32_t k1b = (uint32_t)__cvta_generic_to_shared(&k1s[0][0]);
#pragma unroll
    for (int e = 0; e < 2; e++) {
        int u = tid + e * 128;
        int t = u >> 2, part = u & 3;
        ldgsts16(k1b + (uint32_t)(t * 80 + part * 16), kg + t * 16 + part * 4);
    }
    asm volatile("cp.async.commit_group;\n" ::: "memory");

    // group 1: v planes
    uint32_t vhb = (uint32_t)__cvta_generic_to_shared(&vhs[0][0]);
    uint32_t vlb = (uint32_t)__cvta_generic_to_shared(&vls[0][0]);
#pragma unroll
    for (int e = 0; e < 2; e++) {
        int u = tid + e * 128;
        int t = u >> 2, part = u & 3;
        ldgsts16(vhb + (uint32_t)(t * 80 + part * 16), vhg + t * 16 + part * 4);
        ldgsts16(vlb + (uint32_t)(t * 80 + part * 16), vlg + t * 16 + part * 4);
    }
    asm volatile("cp.async.commit_group;\n" ::: "memory");

    // group 2: bias+mask tile (each warp its own 16 rows)
    uint32_t bmsb = (uint32_t)__cvta_generic_to_shared(&bms[0][0]);
#pragma unroll
    for (int e = 0; e < 8; e++) {
        int i = lane + 32 * e;
        int rr = warp * 16 + (i >> 4);
        int cu = (i & 15) * 4;
        ldgsts16(bmsb + (uint32_t)(rr * 68 + cu) * 4, bmr + rr * 64 + cu);
    }
    asm volatile("cp.async.commit_group;\n" ::: "memory");

    // q hi fragments straight from gmem
    uint32_t qh_[2][4];
#pragma unroll
    for (int ks = 0; ks < 2; ks++) {
        int j0 = ks * 8;
        qh_[ks][0] = qg[(mr + g) * 16 + j0 + tg];
        qh_[ks][1] = qg[(mr + g + 8) * 16 + j0 + tg];
        qh_[ks][2] = qg[(mr + g) * 16 + j0 + tg + 4];
        qh_[ks][3] = qg[(mr + g + 8) * 16 + j0 + tg + 4];
    }

    asm volatile("cp.async.wait_group 2;\n" ::: "memory");
    __syncthreads();

    // logits(log2) = q @ k^T  (single bf16 term)
    float acc[8][4];
#pragma unroll
    for (int a = 0; a < 8; a++)
#pragma unroll
        for (int c = 0; c < 4; c++) acc[a][c] = 0.f;

#pragma unroll
    for (int ks = 0; ks < 2; ks++) {
        int j0 = ks * 8;
#pragma unroll
        for (int nfp = 0; nfp < 4; nfp++) {
            int nf0 = 2 * nfp, nf1 = nf0 + 1;
            int n0 = nf0 * 8 + g;
            uint32_t c0 = k1s[n0][j0 + tg],     c1 = k1s[n0][j0 + tg + 4];
            uint32_t d0 = k1s[n0 + 8][j0 + tg], d1 = k1s[n0 + 8][j0 + tg + 4];
            mma_bf16(acc[nf0], qh_[ks], c0, c1);
            mma_bf16(acc[nf1], qh_[ks], d0, d1);
        }
    }

    asm volatile("cp.async.wait_group 0;\n" ::: "memory");
    __syncthreads();

    int r0 = mr + g, r1 = r0 + 8;
#pragma unroll
    for (int nf = 0; nf < 8; nf++) {
        int n0 = nf * 8 + 2 * tg;
        float2 e0 = *(const float2*)(&bms[r0][n0]);
        float2 e1 = *(const float2*)(&bms[r1][n0]);
        acc[nf][0] += e0.x; acc[nf][1] += e0.y;
        acc[nf][2] += e1.x; acc[nf][3] += e1.y;
    }

    float m0 = -1e30f, m1 = -1e30f;
#pragma unroll
    for (int nf = 0; nf < 8; nf++) {
        m0 = fmaxf(m0, fmaxf(acc[nf][0], acc[nf][1]));
        m1 = fmaxf(m1, fmaxf(acc[nf][2], acc[nf][3]));
    }
    m0 = fmaxf(m0, __shfl_xor_sync(0xffffffffu, m0, 1));
    m0 = fmaxf(m0, __shfl_xor_sync(0xffffffffu, m0, 2));
    m1 = fmaxf(m1, __shfl_xor_sync(0xffffffffu, m1, 1));
    m1 = fmaxf(m1, __shfl_xor_sync(0xffffffffu, m1, 2));

    // unnormalized probs; sums reduce in parallel with P.V
    float s0 = 0.f, s1 = 0.f;
#pragma unroll
    for (int nf = 0; nf < 8; nf++) {
        acc[nf][0] = ex2(acc[nf][0] - m0); s0 += acc[nf][0];
        acc[nf][1] = ex2(acc[nf][1] - m0); s0 += acc[nf][1];
        acc[nf][2] = ex2(acc[nf][2] - m1); s1 += acc[nf][2];
        acc[nf][3] = ex2(acc[nf][3] - m1); s1 += acc[nf][3];
    }

    float oacc[4][4];
#pragma unroll
    for (int a = 0; a < 4; a++)
#pragma unroll
        for (int c = 0; c < 4; c++) oacc[a][c] = 0.f;

    uint32_t vrow = (uint32_t)(((lane >> 3) & 1) * 8 + (lane & 7));
    uint32_t vcol = (uint32_t)((lane >> 4) * 16);
    uint32_t vh_l = vhb + vrow * 80 + vcol;
    uint32_t vl_l = vlb + vrow * 80 + vcol;

#pragma unroll
    for (int ks = 0; ks < 4; ks++) {
        uint32_t ah[4], al[4];
        split2(acc[2 * ks][0],     acc[2 * ks][1],     ah[0], al[0]);
        split2(acc[2 * ks][2],     acc[2 * ks][3],     ah[1], al[1]);
        split2(acc[2 * ks + 1][0], acc[2 * ks + 1][1], ah[2], al[2]);
        split2(acc[2 * ks + 1][2], acc[2 * ks + 1][3], ah[3], al[3]);
        uint32_t ko = (uint32_t)(ks * 16 * 80);
        uint32_t bh0[4], bh1[4], bl0[4], bl1[4];
        ldsm4t(bh0, vh_l + ko);
        ldsm4t(bh1, vh_l + ko + 32);
        ldsm4t(bl0, vl_l + ko);
        ldsm4t(bl1, vl_l + ko + 32);
        mma_bf16(oacc[0], ah, bh0[0], bh0[1]);
        mma_bf16(oacc[1], ah, bh0[2], bh0[3]);
        mma_bf16(oacc[2], ah, bh1[0], bh1[1]);
        mma_bf16(oacc[3], ah, bh1[2], bh1[3]);
        mma_bf16(oacc[0], ah, bl0[0], bl0[1]);
        mma_bf16(oacc[1], ah, bl0[2], bl0[3]);
        mma_bf16(oacc[2], ah, bl1[0], bl1[1]);
        mma_bf16(oacc[3], ah, bl1[2], bl1[3]);
        mma_bf16(oacc[0], al, bh0[0], bh0[1]);
        mma_bf16(oacc[1], al, bh0[2], bh0[3]);
        mma_bf16(oacc[2], al, bh1[0], bh1[1]);
        mma_bf16(oacc[3], al, bh1[2], bh1[3]);
    }

    s0 += __shfl_xor_sync(0xffffffffu, s0, 1);
    s0 += __shfl_xor_sync(0xffffffffu, s0, 2);
    s1 += __shfl_xor_sync(0xffffffffu, s1, 1);
    s1 += __shfl_xor_sync(0xffffffffu, s1, 2);
    float i0 = 1.f / s0, i1 = 1.f / s1;

    int m0r = b * 64 + r0, m1r = b * 64 + r1;
#pragma unroll
    for (int nf = 0; nf < 4; nf++) {
        int dp = h * 16 + nf * 4 + tg;
        int kb = dp >> 4, q = dp & 15;
        uint32_t hi, lo;
        {
            size_t idx = ((size_t)((m0r >> 7) * 8 + kb)) * 2048 + plane_pair(m0r & 127, q);
            split2(oacc[nf][0] * i0, oacc[nf][1] * i0, hi, lo);
            g_othi[idx] = hi; g_otlo[idx] = lo;
        }
        {
            size_t idx = ((size_t)((m1r >> 7) * 8 + kb)) * 2048 + plane_pair(m1r & 127, q);
            split2(oacc[nf][2] * i1, oacc[nf][3] * i1, hi, lo);
            g_othi[idx] = hi; g_otlo[idx] = lo;
        }
    }
}

// ---------------------------------------------------------------------------
extern "C" void kernel_launch(void* const* d_in, const int* in_sizes, int n_in,
                              void* d_out, int out_size) {
    (void)in_sizes; (void)n_in; (void)out_size;
    const float* x       = (const float*)d_in[0];
    const float* mask    = (const float*)d_in[1];
    const float* qkv_w   = (const float*)d_in[2];
    const float* qkv_b   = (const float*)d_in[3];
    const float* proj_w  = (const float*)d_in[4];
    const float* proj_b  = (const float*)d_in[5];
    const float* pposw   = (const float*)d_in[6];
    const float* pposb   = (const float*)d_in[7];
    const float* ln1g    = (const float*)d_in[8];
    const float* ln1b    = (const float*)d_in[9];
    const float* fc1w    = (const float*)d_in[10];
    const float* fc1b    = (const float*)d_in[11];
    const float* ln2g    = (const float*)d_in[12];
    const float* ln2b    = (const float*)d_in[13];
    const float* fc2w    = (const float*)d_in[14];
    const float* fc2b    = (const float*)d_in[15];
    const float* ln3g    = (const float*)d_in[16];
    const float* ln3b    = (const float*)d_in[17];
    const float* fc3w    = (const float*)d_in[18];
    const float* fc3b    = (const float*)d_in[19];
    const float* biases  = (const float*)d_in[20];
    const int*   rel_idx = (const int*)d_in[21];
    float* out = (float*)d_out;

    static bool attr_set = false;
    if (!attr_set) {
        cudaFuncSetAttribute(gemm_kernel<0>, cudaFuncAttributeMaxDynamicSharedMemorySize, 98304);
        cudaFuncSetAttribute(gemm_kernel<1>, cudaFuncAttributeMaxDynamicSharedMemorySize, 98304);
        attr_set = true;
    }

    dpb_kernel<<<1, 256>>>(biases, pposw, pposb, ln1g, ln1b, fc1w, fc1b,
                           ln2g, ln2b, fc2w, fc2b, ln3g, ln3b, fc3w, fc3b);
    presplit_kernel<<<50432, 256>>>(x, qkv_w, proj_w);
    bmtab_kernel<<<dim3(NW, HEADS), 256>>>(mask, rel_idx);
    gemm_kernel<0><<<dim3(6, 1568), 256, 98304>>>(qkv_b, nullptr);
    attn_kernel<<<dim3(B_WIN, HEADS), 128>>>();
    gemm_kernel<1><<<dim3(2, 1568), 256, 98304>>>(proj_b, out);
}

// round 16
// speedup vs baseline: 1.4917x; 1.4190x over previous
#include <cuda_runtime.h>
#include <cuda_bf16.h>
#include <cuda_fp16.h>
#include <cstdint>
#include <math.h>

#define B_WIN   3136
#define NTOK    64
#define DIM     256
#define HEADS   8
#define NW      49
#define LBIAS   225
#define ATT_SCALE 0.17677669529663687f  // 1/sqrt(32)
#define LOG2E   1.4426950408889634f
#define ATT_SCALE_L2E (0.17677669529663687f * 1.4426950408889634f)

// ---------------------------------------------------------------------------
// Plane layout (see R7): per (tile128, kchunk32) chunk, 2048 uint32 pairs.
// qkv leg: single fp16 planes. proj leg: bf16 hi/lo planes (bf16x3).
// ---------------------------------------------------------------------------
__device__ uint32_t g_xf  [25690112];  // x fp16 plane
__device__ uint32_t g_wqf [98304];     // qkv_w fp16 plane
__device__ uint32_t g_othi[25690112];  // ctx bf16 hi plane
__device__ uint32_t g_otlo[25690112];
__device__ uint32_t g_wph [32768];
__device__ uint32_t g_wpl [32768];
__device__ uint32_t g_q1  [25690112];  // q hi-only bf16x2/pair (log2e-scaled)
__device__ uint32_t g_k1  [25690112];  // k hi-only
__device__ uint32_t g_vh  [25690112];  // v hi plane
__device__ uint32_t g_vl  [25690112];  // v lo plane
__device__ float    g_ptab[LBIAS * HEADS];
__device__ float    g_bm  [1605632];   // (bias+mask)*log2e  [49][8][64][64]

// ---------------------------------------------------------------------------
__device__ __forceinline__ void split2(float x, float y, uint32_t& hi, uint32_t& lo) {
    __nv_bfloat162 h = __floats2bfloat162_rn(x, y);
    float hx = __low2float(h), hy = __high2float(h);
    __nv_bfloat162 l = __floats2bfloat162_rn(x - hx, y - hy);
    hi = *reinterpret_cast<uint32_t*>(&h);
    lo = *reinterpret_cast<uint32_t*>(&l);
}

__device__ __forceinline__ uint32_t pack_hi(float x, float y) {
    __nv_bfloat162 h = __floats2bfloat162_rn(x, y);
    return *reinterpret_cast<uint32_t*>(&h);
}

__device__ __forceinline__ uint32_t pack_f16(float x, float y) {
    __half2 h = __floats2half2_rn(x, y);
    return *reinterpret_cast<uint32_t*>(&h);
}

__device__ __forceinline__ uint32_t plane_pair(int r, int q) {
    int j = r >> 1;
    int u = (((r & 1) << 2) | (q >> 2)) ^ (j & 7);
    return (uint32_t)(j * 32 + u * 4 + (q & 3));
}

__device__ __forceinline__ void mma_bf16(float* c, const uint32_t* a, uint32_t b0, uint32_t b1) {
    asm volatile(
        "mma.sync.aligned.m16n8k16.row.col.f32.bf16.bf16.f32 "
        "{%0,%1,%2,%3}, {%4,%5,%6,%7}, {%8,%9}, {%0,%1,%2,%3};\n"
        : "+f"(c[0]), "+f"(c[1]), "+f"(c[2]), "+f"(c[3])
        : "r"(a[0]), "r"(a[1]), "r"(a[2]), "r"(a[3]), "r"(b0), "r"(b1));
}

__device__ __forceinline__ void mma_f16(float* c, const uint32_t* a, uint32_t b0, uint32_t b1) {
    asm volatile(
        "mma.sync.aligned.m16n8k16.row.col.f32.f16.f16.f32 "
        "{%0,%1,%2,%3}, {%4,%5,%6,%7}, {%8,%9}, {%0,%1,%2,%3};\n"
        : "+f"(c[0]), "+f"(c[1]), "+f"(c[2]), "+f"(c[3])
        : "r"(a[0]), "r"(a[1]), "r"(a[2]), "r"(a[3]), "r"(b0), "r"(b1));
}

__device__ __forceinline__ void ldsm4(uint32_t* r, uint32_t a) {
    asm volatile("ldmatrix.sync.aligned.m8n8.x4.shared.b16 {%0,%1,%2,%3}, [%4];"
                 : "=r"(r[0]), "=r"(r[1]), "=r"(r[2]), "=r"(r[3]) : "r"(a));
}

__device__ __forceinline__ void ldsm4t(uint32_t* r, uint32_t a) {
    asm volatile("ldmatrix.sync.aligned.m8n8.x4.trans.shared.b16 {%0,%1,%2,%3}, [%4];"
                 : "=r"(r[0]), "=r"(r[1]), "=r"(r[2]), "=r"(r[3]) : "r"(a));
}

__device__ __forceinline__ void ldgsts16(uint32_t saddr, const void* gp) {
    asm volatile("cp.async.cg.shared.global [%0], [%1], 16;\n" :: "r"(saddr), "l"(gp));
}

__device__ __forceinline__ float ex2(float x) {
    float y;
    asm("ex2.approx.f32 %0, %1;" : "=f"(y) : "f"(x));
    return y;
}

// ---------------------------------------------------------------------------
// Kernel 1: DynamicPosBias MLP -> g_ptab[225][8]
// ---------------------------------------------------------------------------
__device__ __forceinline__ void lnrelu16(const float* p, float* t,
                                         const float* gm, const float* bt) {
    float m = 0.f;
#pragma unroll
    for (int j = 0; j < 16; j++) m += p[j];
    m *= (1.f / 16.f);
    float v = 0.f;
#pragma unroll
    for (int j = 0; j < 16; j++) { float d = p[j] - m; v += d * d; }
    v *= (1.f / 16.f);
    float is = rsqrtf(v + 1e-5f);
#pragma unroll
    for (int j = 0; j < 16; j++) {
        float u = (p[j] - m) * is * gm[j] + bt[j];
        t[j] = u > 0.f ? u : 0.f;
    }
}

__global__ void dpb_kernel(const float* __restrict__ biases,
                           const float* __restrict__ pw, const float* __restrict__ pb,
                           const float* __restrict__ g1, const float* __restrict__ b1,
                           const float* __restrict__ w1, const float* __restrict__ c1,
                           const float* __restrict__ g2, const float* __restrict__ b2,
                           const float* __restrict__ w2, const float* __restrict__ c2,
                           const float* __restrict__ g3, const float* __restrict__ b3,
                           const float* __restrict__ w3, const float* __restrict__ c3) {
    int r = threadIdx.x;
    if (r >= LBIAS) return;
    float p[16], t[16];
    float x0 = biases[2 * r], x1 = biases[2 * r + 1];
#pragma unroll
    for (int j = 0; j < 16; j++) p[j] = x0 * pw[2 * j] + x1 * pw[2 * j + 1] + pb[j];
    lnrelu16(p, t, g1, b1);
#pragma unroll
    for (int o = 0; o < 16; o++) {
        float s = c1[o];
#pragma unroll
        for (int j = 0; j < 16; j++) s += t[j] * w1[o * 16 + j];
        p[o] = s;
    }
    lnrelu16(p, t, g2, b2);
#pragma unroll
    for (int o = 0; o < 16; o++) {
        float s = c2[o];
#pragma unroll
        for (int j = 0; j < 16; j++) s += t[j] * w2[o * 16 + j];
        p[o] = s;
    }
    lnrelu16(p, t, g3, b3);
#pragma unroll
    for (int o = 0; o < 8; o++) {
        float s = c3[o];
#pragma unroll
        for (int j = 0; j < 16; j++) s += t[j] * w3[o * 16 + j];
        g_ptab[r * 8 + o] = s;
    }
}

// ---------------------------------------------------------------------------
// Kernel 1b: presplit. x,qkv_w -> single fp16 planes; proj_w -> bf16 hi/lo.
// ---------------------------------------------------------------------------
__global__ void presplit_kernel(const float* __restrict__ x,
                                const float* __restrict__ qw,
                                const float* __restrict__ pw) {
    long i = (long)blockIdx.x * 256 + threadIdx.x;  // handles pairs 2i, 2i+1
    int kind; const float4* src; long j2;
    if (i < 12845056L) { kind = 0; j2 = 2 * i; src = (const float4*)x; }
    else if (i < 12845056L + 49152) { kind = 1; j2 = 2 * (i - 12845056L); src = (const float4*)qw; }
    else if (i < 12845056L + 49152 + 16384) { kind = 2; j2 = 2 * (i - 12845056L - 49152); src = (const float4*)pw; }
    else return;
    float4 f = src[j2 >> 1];
    int m = (int)(j2 >> 7);
    int pc = (int)(j2 & 127);           // even
    int tile = m >> 7, r = m & 127;
    int kb = pc >> 4, q = pc & 15;      // q even -> idx, idx+1 consecutive
    long idx = ((long)(tile * 8 + kb)) * 2048 + plane_pair(r, q);
    if (kind == 0) {
        *(uint2*)(g_xf + idx) = make_uint2(pack_f16(f.x, f.y), pack_f16(f.z, f.w));
    } else if (kind == 1) {
        *(uint2*)(g_wqf + idx) = make_uint2(pack_f16(f.x, f.y), pack_f16(f.z, f.w));
    } else {
        uint32_t h0, l0, h1, l1;
        split2(f.x, f.y, h0, l0);
        split2(f.z, f.w, h1, l1);
        *(uint2*)(g_wph + idx) = make_uint2(h0, h1);
        *(uint2*)(g_wpl + idx) = make_uint2(l0, l1);
    }
}

// ---------------------------------------------------------------------------
// Kernel 1c: combined (bias+mask)*log2e table
// ---------------------------------------------------------------------------
__global__ void bmtab_kernel(const float* __restrict__ mask,
                             const int* __restrict__ rel_idx) {
    int wb = blockIdx.x, h = blockIdx.y;
    float* dst = g_bm + (size_t)(wb * 8 + h) * 4096;
    const float* msk = mask + (size_t)wb * 4096;
    for (int i = threadIdx.x; i < 4096; i += blockDim.x)
        dst[i] = (g_ptab[rel_idx[i] * 8 + h] + msk[i]) * LOG2E;
}

// ---------------------------------------------------------------------------
// Kernel 2: qkv GEMM, fp16 single-term. BM=BN=128, K=256 in 8 chunks of 32.
// 16KB/stage, 3 stages. Epilogue scatters q/k (hi bf16) and v (bf16 split).
// ---------------------------------------------------------------------------
__global__ __launch_bounds__(256, 2) void gemm_qkv(const float* __restrict__ bias) {
    extern __shared__ char smem[];
    uint32_t sb = (uint32_t)__cvta_generic_to_shared(smem);

    int bm = blockIdx.y, bn = blockIdx.x;
    int tid = threadIdx.x;
    int warp = tid >> 5, lane = tid & 31;
    int wm = warp >> 1, wn = warp & 1;
    int g = lane >> 2, tg = lane & 3;

    float acc[2][8][4];
#pragma unroll
    for (int a = 0; a < 2; a++)
#pragma unroll
        for (int b = 0; b < 8; b++)
#pragma unroll
            for (int c = 0; c < 4; c++) acc[a][b][c] = 0.f;

    auto mkbase = [&](int r, int lb) {
        int j = r >> 1, a = (r & 1) << 2;
        return (uint32_t)(j * 128 + (((a ^ lb) ^ (j & 7)) << 4));
    };
    int rA = lane & 15, lbA = lane >> 4;
    uint32_t baseA0 = mkbase(wm * 32 + rA, lbA);
    uint32_t baseA1 = mkbase(wm * 32 + 16 + rA, lbA);
    int rB = (lane & 7) | ((lane >> 1) & 8);
    int lbB = (lane >> 3) & 1;
    uint32_t baseB[4];
#pragma unroll
    for (int i = 0; i < 4; i++) baseB[i] = mkbase(wn * 64 + i * 16 + rB, lbB);

    auto issue = [&](int kb, int s) {
        uint32_t S = sb + (uint32_t)s * 16384;
        const uint32_t* srcA = g_xf + (size_t)(bm * 8 + kb) * 2048;
        const uint32_t* srcB = g_wqf + (size_t)(bn * 8 + kb) * 2048;
#pragma unroll
        for (int e = 0; e < 2; e++) {
            int u = tid + e * 256;
            ldgsts16(S + u * 16, srcA + u * 4);
            ldgsts16(S + 8192 + u * 16, srcB + u * 4);
        }
        asm volatile("cp.async.commit_group;\n" ::: "memory");
    };

    issue(0, 0);
    issue(1, 1);

    for (int kb = 0; kb < 8; kb++) {
        int s = kb % 3;
        if (kb < 7) asm volatile("cp.async.wait_group 1;\n" ::: "memory");
        else        asm volatile("cp.async.wait_group 0;\n" ::: "memory");
        __syncthreads();

        uint32_t S = sb + (uint32_t)s * 16384;
#pragma unroll
        for (int ks = 0; ks < 2; ks++) {
            uint32_t uo = ks * 32;
            uint32_t a0[4], a1[4];
            ldsm4(a0, S + (baseA0 ^ uo));
            ldsm4(a1, S + (baseA1 ^ uo));
#pragma unroll
            for (int nfp = 0; nfp < 4; nfp++) {
                int nf0 = 2 * nfp, nf1 = nf0 + 1;
                uint32_t bh[4];
                ldsm4(bh, S + 8192 + (baseB[nfp] ^ uo));
                mma_f16(acc[0][nf0], a0, bh[0], bh[1]);
                mma_f16(acc[1][nf0], a1, bh[0], bh[1]);
                mma_f16(acc[0][nf1], a0, bh[2], bh[3]);
                mma_f16(acc[1][nf1], a1, bh[2], bh[3]);
            }
        }
        if (kb < 6) issue(kb + 2, (kb + 2) % 3);
    }

    int obase = bn * 128 + wn * 64;
#pragma unroll
    for (int nf = 0; nf < 8; nf++) {
        int o = obase + nf * 8 + 2 * tg;
        float bb0 = bias[o], bb1 = bias[o + 1];
#pragma unroll
        for (int mf = 0; mf < 2; mf++) {
#pragma unroll
            for (int r2 = 0; r2 < 2; r2++) {
                int m = bm * 128 + wm * 32 + mf * 16 + g + r2 * 8;
                float v0 = acc[mf][nf][r2 * 2] + bb0;
                float v1 = acc[mf][nf][r2 * 2 + 1] + bb1;
                int s = o >> 8, hh = (o >> 5) & 7, d = o & 31;
                int bw = m >> 6, n = m & 63;
                size_t di = ((size_t)(bw * 8 + hh) * 64 + n) * 16 + (d >> 1);
                uint32_t hi, lo;
                if (s == 0)      { g_q1[di] = pack_hi(v0 * ATT_SCALE_L2E, v1 * ATT_SCALE_L2E); }
                else if (s == 1) { g_k1[di] = pack_hi(v0, v1); }
                else             { split2(v0, v1, hi, lo); g_vh[di] = hi; g_vl[di] = lo; }
            }
        }
    }
}

// ---------------------------------------------------------------------------
// Kernel 4: proj GEMM, bf16x3 (R13-exact mainloop).
// ---------------------------------------------------------------------------
__global__ __launch_bounds__(256, 2) void gemm_proj(const float* __restrict__ bias,
                                                    float* __restrict__ Out) {
    extern __shared__ char smem[];
    uint32_t sb = (uint32_t)__cvta_generic_to_shared(smem);

    int bm = blockIdx.y, bn = blockIdx.x;
    int tid = threadIdx.x;
    int warp = tid >> 5, lane = tid & 31;
    int wm = warp >> 1, wn = warp & 1;
    int g = lane >> 2, tg = lane & 3;

    float acc[2][8][4];
#pragma unroll
    for (int a = 0; a < 2; a++)
#pragma unroll
        for (int b = 0; b < 8; b++)
#pragma unroll
            for (int c = 0; c < 4; c++) acc[a][b][c] = 0.f;

    auto mkbase = [&](int r, int lb) {
        int j = r >> 1, a = (r & 1) << 2;
        return (uint32_t)(j * 128 + (((a ^ lb) ^ (j & 7)) << 4));
    };
    int rA = lane & 15, lbA = lane >> 4;
    uint32_t baseA0 = mkbase(wm * 32 + rA, lbA);
    uint32_t baseA1 = mkbase(wm * 32 + 16 + rA, lbA);
    int rB = (lane & 7) | ((lane >> 1) & 8);
    int lbB = (lane >> 3) & 1;
    uint32_t baseB[4];
#pragma unroll
    for (int i = 0; i < 4; i++) baseB[i] = mkbase(wn * 64 + i * 16 + rB, lbB);

    auto issue = [&](int kb, int s) {
        uint32_t S = sb + (uint32_t)s * 32768;
        const uint32_t* srcs[4] = {
            g_othi + (size_t)(bm * 8 + kb) * 2048, g_otlo + (size_t)(bm * 8 + kb) * 2048,
            g_wph + (size_t)(bn * 8 + kb) * 2048,  g_wpl + (size_t)(bn * 8 + kb) * 2048 };
#pragma unroll
        for (int p = 0; p < 4; p++) {
#pragma unroll
            for (int e = 0; e < 2; e++) {
                int u = tid + e * 256;
                ldgsts16(S + (uint32_t)p * 8192 + u * 16, srcs[p] + u * 4);
            }
        }
        asm volatile("cp.async.commit_group;\n" ::: "memory");
    };

    issue(0, 0);
    issue(1, 1);

    for (int kb = 0; kb < 8; kb++) {
        int s = kb % 3;
        if (kb < 7) asm volatile("cp.async.wait_group 1;\n" ::: "memory");
        else        asm volatile("cp.async.wait_group 0;\n" ::: "memory");
        __syncthreads();

        uint32_t S = sb + (uint32_t)s * 32768;
#pragma unroll
        for (int ks = 0; ks < 2; ks++) {
            uint32_t uo = ks * 32;
            uint32_t ah0[4], ah1[4], al0[4], al1[4];
            ldsm4(ah0, S + (baseA0 ^ uo));
            ldsm4(ah1, S + (baseA1 ^ uo));
            ldsm4(al0, S + 8192 + (baseA0 ^ uo));
            ldsm4(al1, S + 8192 + (baseA1 ^ uo));
#pragma unroll
            for (int nfp = 0; nfp < 4; nfp++) {
                int nf0 = 2 * nfp, nf1 = nf0 + 1;
                uint32_t bh[4], bl[4];
                ldsm4(bh, S + 16384 + (baseB[nfp] ^ uo));
                ldsm4(bl, S + 24576 + (baseB[nfp] ^ uo));
                mma_bf16(acc[0][nf0], ah0, bh[0], bh[1]);
                mma_bf16(acc[1][nf0], ah1, bh[0], bh[1]);
                mma_bf16(acc[0][nf1], ah0, bh[2], bh[3]);
                mma_bf16(acc[1][nf1], ah1, bh[2], bh[3]);
                mma_bf16(acc[0][nf0], ah0, bl[0], bl[1]);
                mma_bf16(acc[1][nf0], ah1, bl[0], bl[1]);
                mma_bf16(acc[0][nf1], ah0, bl[2], bl[3]);
                mma_bf16(acc[1][nf1], ah1, bl[2], bl[3]);
                mma_bf16(acc[0][nf0], al0, bh[0], bh[1]);
                mma_bf16(acc[1][nf0], al1, bh[0], bh[1]);
                mma_bf16(acc[0][nf1], al0, bh[2], bh[3]);
                mma_bf16(acc[1][nf1], al1, bh[2], bh[3]);
            }
        }
        if (kb < 6) issue(kb + 2, (kb + 2) % 3);
    }

    int obase = bn * 128 + wn * 64;
#pragma unroll
    for (int nf = 0; nf < 8; nf++) {
        int o = obase + nf * 8 + 2 * tg;
        float bb0 = bias[o], bb1 = bias[o + 1];
#pragma unroll
        for (int mf = 0; mf < 2; mf++) {
#pragma unroll
            for (int r2 = 0; r2 < 2; r2++) {
                int m = bm * 128 + wm * 32 + mf * 16 + g + r2 * 8;
                float v0 = acc[mf][nf][r2 * 2] + bb0;
                float v1 = acc[mf][nf][r2 * 2 + 1] + bb1;
                *(float2*)(Out + (size_t)m * 256 + o) = make_float2(v0, v1);
            }
        }
    }
}

// ---------------------------------------------------------------------------
// Kernel 3: attention (R15-exact). q/k hi-only bf16; P.V bf16x3; deferred norm.
// ---------------------------------------------------------------------------
__global__ __launch_bounds__(128, 6) void attn_kernel() {
    __shared__ uint32_t k1s[64][20];
    __shared__ uint32_t vhs[64][20];
    __shared__ uint32_t vls[64][20];
    __shared__ float    bms[64][68];

    int b = blockIdx.x, h = blockIdx.y;
    int tid = threadIdx.x;
    int warp = tid >> 5, lane = tid & 31;
    int g = lane >> 2, tg = lane & 3;
    int mr = warp * 16;

    const uint32_t* qg = g_q1 + (size_t)(b * 8 + h) * 1024;
    const uint32_t* kg = g_k1 + (size_t)(b * 8 + h) * 1024;
    const uint32_t* vhg = g_vh + (size_t)(b * 8 + h) * 1024;
    const uint32_t* vlg = g_vl + (size_t)(b * 8 + h) * 1024;
    const float*    bmr = g_bm + (size_t)((b % NW) * 8 + h) * 4096;

    uint32_t k1b = (uint32_t)__cvta_generic_to_shared(&k1s[0][0]);
#pragma unroll
    for (int e = 0; e < 2; e++) {
        int u = tid + e * 128;
        int t = u >> 2, part = u & 3;
        ldgsts16(k1b + (uint32_t)(t * 80 + part * 16), kg + t * 16 + part * 4);
    }
    asm volatile("cp.async.commit_group;\n" ::: "memory");

    uint32_t vhb = (uint32_t)__cvta_generic_to_shared(&vhs[0][0]);
    uint32_t vlb = (uint32_t)__cvta_generic_to_shared(&vls[0][0]);
#pragma unroll
    for (int e = 0; e < 2; e++) {
        int u = tid + e * 128;
        int t = u >> 2, part = u & 3;
        ldgsts16(vhb + (uint32_t)(t * 80 + part * 16), vhg + t * 16 + part * 4);
        ldgsts16(vlb + (uint32_t)(t * 80 + part * 16), vlg + t * 16 + part * 4);
    }
    asm volatile("cp.async.commit_group;\n" ::: "memory");

    uint32_t bmsb = (uint32_t)__cvta_generic_to_shared(&bms[0][0]);
#pragma unroll
    for (int e = 0; e < 8; e++) {
        int i = lane + 32 * e;
        int rr = warp * 16 + (i >> 4);
        int cu = (i & 15) * 4;
        ldgsts16(bmsb + (uint32_t)(rr * 68 + cu) * 4, bmr + rr * 64 + cu);
    }
    asm volatile("cp.async.commit_group;\n" ::: "memory");

    uint32_t qh_[2][4];
#pragma unroll
    for (int ks = 0; ks < 2; ks++) {
        int j0 = ks * 8;
        qh_[ks][0] = qg[(mr + g) * 16 + j0 + tg];
        qh_[ks][1] = qg[(mr + g + 8) * 16 + j0 + tg];
        qh_[ks][2] = qg[(mr + g) * 16 + j0 + tg + 4];
        qh_[ks][3] = qg[(mr + g + 8) * 16 + j0 + tg + 4];
    }

    asm volatile("cp.async.wait_group 2;\n" ::: "memory");
    __syncthreads();

    float acc[8][4];
#pragma unroll
    for (int a = 0; a < 8; a++)
#pragma unroll
        for (int c = 0; c < 4; c++) acc[a][c] = 0.f;

#pragma unroll
    for (int ks = 0; ks < 2; ks++) {
        int j0 = ks * 8;
#pragma unroll
        for (int nfp = 0; nfp < 4; nfp++) {
            int nf0 = 2 * nfp, nf1 = nf0 + 1;
            int n0 = nf0 * 8 + g;
            uint32_t c0 = k1s[n0][j0 + tg],     c1 = k1s[n0][j0 + tg + 4];
            uint32_t d0 = k1s[n0 + 8][j0 + tg], d1 = k1s[n0 + 8][j0 + tg + 4];
            mma_bf16(acc[nf0], qh_[ks], c0, c1);
            mma_bf16(acc[nf1], qh_[ks], d0, d1);
        }
    }

    asm volatile("cp.async.wait_group 0;\n" ::: "memory");
    __syncthreads();

    int r0 = mr + g, r1 = r0 + 8;
#pragma unroll
    for (int nf = 0; nf < 8; nf++) {
        int n0 = nf * 8 + 2 * tg;
        float2 e0 = *(const float2*)(&bms[r0][n0]);
        float2 e1 = *(const float2*)(&bms[r1][n0]);
        acc[nf][0] += e0.x; acc[nf][1] += e0.y;
        acc[nf][2] += e1.x; acc[nf][3] += e1.y;
    }

    float m0 = -1e30f, m1 = -1e30f;
#pragma unroll
    for (int nf = 0; nf < 8; nf++) {
        m0 = fmaxf(m0, fmaxf(acc[nf][0], acc[nf][1]));
        m1 = fmaxf(m1, fmaxf(acc[nf][2], acc[nf][3]));
    }
    m0 = fmaxf(m0, __shfl_xor_sync(0xffffffffu, m0, 1));
    m0 = fmaxf(m0, __shfl_xor_sync(0xffffffffu, m0, 2));
    m1 = fmaxf(m1, __shfl_xor_sync(0xffffffffu, m1, 1));
    m1 = fmaxf(m1, __shfl_xor_sync(0xffffffffu, m1, 2));

    float s0 = 0.f, s1 = 0.f;
#pragma unroll
    for (int nf = 0; nf < 8; nf++) {
        acc[nf][0] = ex2(acc[nf][0] - m0); s0 += acc[nf][0];
        acc[nf][1] = ex2(acc[nf][1] - m0); s0 += acc[nf][1];
        acc[nf][2] = ex2(acc[nf][2] - m1); s1 += acc[nf][2];
        acc[nf][3] = ex2(acc[nf][3] - m1); s1 += acc[nf][3];
    }

    float oacc[4][4];
#pragma unroll
    for (int a = 0; a < 4; a++)
#pragma unroll
        for (int c = 0; c < 4; c++) oacc[a][c] = 0.f;

    uint32_t vrow = (uint32_t)(((lane >> 3) & 1) * 8 + (lane & 7));
    uint32_t vcol = (uint32_t)((lane >> 4) * 16);
    uint32_t vh_l = vhb + vrow * 80 + vcol;
    uint32_t vl_l = vlb + vrow * 80 + vcol;

#pragma unroll
    for (int ks = 0; ks < 4; ks++) {
        uint32_t ah[4], al[4];
        split2(acc[2 * ks][0],     acc[2 * ks][1],     ah[0], al[0]);
        split2(acc[2 * ks][2],     acc[2 * ks][3],     ah[1], al[1]);
        split2(acc[2 * ks + 1][0], acc[2 * ks + 1][1], ah[2], al[2]);
        split2(acc[2 * ks + 1][2], acc[2 * ks + 1][3], ah[3], al[3]);
        uint32_t ko = (uint32_t)(ks * 16 * 80);
        uint32_t bh0[4], bh1[4], bl0[4], bl1[4];
        ldsm4t(bh0, vh_l + ko);
        ldsm4t(bh1, vh_l + ko + 32);
        ldsm4t(bl0, vl_l + ko);
        ldsm4t(bl1, vl_l + ko + 32);
        mma_bf16(oacc[0], ah, bh0[0], bh0[1]);
        mma_bf16(oacc[1], ah, bh0[2], bh0[3]);
        mma_bf16(oacc[2], ah, bh1[0], bh1[1]);
        mma_bf16(oacc[3], ah, bh1[2], bh1[3]);
        mma_bf16(oacc[0], ah, bl0[0], bl0[1]);
        mma_bf16(oacc[1], ah, bl0[2], bl0[3]);
        mma_bf16(oacc[2], ah, bl1[0], bl1[1]);
        mma_bf16(oacc[3], ah, bl1[2], bl1[3]);
        mma_bf16(oacc[0], al, bh0[0], bh0[1]);
        mma_bf16(oacc[1], al, bh0[2], bh0[3]);
        mma_bf16(oacc[2], al, bh1[0], bh1[1]);
        mma_bf16(oacc[3], al, bh1[2], bh1[3]);
    }

    s0 += __shfl_xor_sync(0xffffffffu, s0, 1);
    s0 += __shfl_xor_sync(0xffffffffu, s0, 2);
    s1 += __shfl_xor_sync(0xffffffffu, s1, 1);
    s1 += __shfl_xor_sync(0xffffffffu, s1, 2);
    float i0 = 1.f / s0, i1 = 1.f / s1;

    int m0r = b * 64 + r0, m1r = b * 64 + r1;
#pragma unroll
    for (int nf = 0; nf < 4; nf++) {
        int dp = h * 16 + nf * 4 + tg;
        int kb = dp >> 4, q = dp & 15;
        uint32_t hi, lo;
        {
            size_t idx = ((size_t)((m0r >> 7) * 8 + kb)) * 2048 + plane_pair(m0r & 127, q);
            split2(oacc[nf][0] * i0, oacc[nf][1] * i0, hi, lo);
            g_othi[idx] = hi; g_otlo[idx] = lo;
        }
        {
            size_t idx = ((size_t)((m1r >> 7) * 8 + kb)) * 2048 + plane_pair(m1r & 127, q);
            split2(oacc[nf][2] * i1, oacc[nf][3] * i1, hi, lo);
            g_othi[idx] = hi; g_otlo[idx] = lo;
        }
    }
}

// ---------------------------------------------------------------------------
extern "C" void kernel_launch(void* const* d_in, const int* in_sizes, int n_in,
                              void* d_out, int out_size) {
    (void)in_sizes; (void)n_in; (void)out_size;
    const float* x       = (const float*)d_in[0];
    const float* mask    = (const float*)d_in[1];
    const float* qkv_w   = (const float*)d_in[2];
    const float* qkv_b   = (const float*)d_in[3];
    const float* proj_w  = (const float*)d_in[4];
    const float* proj_b  = (const float*)d_in[5];
    const float* pposw   = (const float*)d_in[6];
    const float* pposb   = (const float*)d_in[7];
    const float* ln1g    = (const float*)d_in[8];
    const float* ln1b    = (const float*)d_in[9];
    const float* fc1w    = (const float*)d_in[10];
    const float* fc1b    = (const float*)d_in[11];
    const float* ln2g    = (const float*)d_in[12];
    const float* ln2b    = (const float*)d_in[13];
    const float* fc2w    = (const float*)d_in[14];
    const float* fc2b    = (const float*)d_in[15];
    const float* ln3g    = (const float*)d_in[16];
    const float* ln3b    = (const float*)d_in[17];
    const float* fc3w    = (const float*)d_in[18];
    const float* fc3b    = (const float*)d_in[19];
    const float* biases  = (const float*)d_in[20];
    const int*   rel_idx = (const int*)d_in[21];
    float* out = (float*)d_out;

    static bool attr_set = false;
    if (!attr_set) {
        cudaFuncSetAttribute(gemm_qkv, cudaFuncAttributeMaxDynamicSharedMemorySize, 49152);
        cudaFuncSetAttribute(gemm_proj, cudaFuncAttributeMaxDynamicSharedMemorySize, 98304);
        attr_set = true;
    }

    dpb_kernel<<<1, 256>>>(biases, pposw, pposb, ln1g, ln1b, fc1w, fc1b,
                           ln2g, ln2b, fc2w, fc2b, ln3g, ln3b, fc3w, fc3b);
    presplit_kernel<<<50432, 256>>>(x, qkv_w, proj_w);
    bmtab_kernel<<<dim3(NW, HEADS), 256>>>(mask, rel_idx);
    gemm_qkv<<<dim3(6, 1568), 256, 49152>>>(qkv_b);
    attn_kernel<<<dim3(B_WIN, HEADS), 128>>>();
    gemm_proj<<<dim3(2, 1568), 256, 98304>>>(proj_b, out);
}

// round 17
// speedup vs baseline: 1.7828x; 1.1951x over previous
#include <cuda_runtime.h>
#include <cuda_bf16.h>
#include <cuda_fp16.h>
#include <cstdint>
#include <math.h>

#define B_WIN   3136
#define NTOK    64
#define DIM     256
#define HEADS   8
#define NW      49
#define LBIAS   225
#define ATT_SCALE 0.17677669529663687f  // 1/sqrt(32)
#define LOG2E   1.4426950408889634f
#define ATT_SCALE_L2E (0.17677669529663687f * 1.4426950408889634f)

// ---------------------------------------------------------------------------
// Plane layout (see R7): per (tile128, kchunk32) chunk, 2048 uint32 pairs.
// qkv and proj legs: single fp16 planes.
// ---------------------------------------------------------------------------
__device__ uint32_t g_xf  [25690112];  // x fp16 plane
__device__ uint32_t g_wqf [98304];     // qkv_w fp16 plane
__device__ uint32_t g_otf [25690112];  // ctx fp16 plane
__device__ uint32_t g_wpf [32768];     // proj_w fp16 plane
__device__ uint32_t g_q1  [25690112];  // q hi-only bf16x2/pair (log2e-scaled)
__device__ uint32_t g_k1  [25690112];  // k hi-only
__device__ uint32_t g_vh  [25690112];  // v hi plane (bf16)
__device__ uint32_t g_vl  [25690112];  // v lo plane
__device__ float    g_ptab[LBIAS * HEADS];
__device__ float    g_bm  [1605632];   // (bias+mask)*log2e  [49][8][64][64]

// ---------------------------------------------------------------------------
__device__ __forceinline__ void split2(float x, float y, uint32_t& hi, uint32_t& lo) {
    __nv_bfloat162 h = __floats2bfloat162_rn(x, y);
    float hx = __low2float(h), hy = __high2float(h);
    __nv_bfloat162 l = __floats2bfloat162_rn(x - hx, y - hy);
    hi = *reinterpret_cast<uint32_t*>(&h);
    lo = *reinterpret_cast<uint32_t*>(&l);
}

__device__ __forceinline__ uint32_t pack_hi(float x, float y) {
    __nv_bfloat162 h = __floats2bfloat162_rn(x, y);
    return *reinterpret_cast<uint32_t*>(&h);
}

__device__ __forceinline__ uint32_t pack_f16(float x, float y) {
    __half2 h = __floats2half2_rn(x, y);
    return *reinterpret_cast<uint32_t*>(&h);
}

__device__ __forceinline__ uint32_t plane_pair(int r, int q) {
    int j = r >> 1;
    int u = (((r & 1) << 2) | (q >> 2)) ^ (j & 7);
    return (uint32_t)(j * 32 + u * 4 + (q & 3));
}

__device__ __forceinline__ void mma_bf16(float* c, const uint32_t* a, uint32_t b0, uint32_t b1) {
    asm volatile(
        "mma.sync.aligned.m16n8k16.row.col.f32.bf16.bf16.f32 "
        "{%0,%1,%2,%3}, {%4,%5,%6,%7}, {%8,%9}, {%0,%1,%2,%3};\n"
        : "+f"(c[0]), "+f"(c[1]), "+f"(c[2]), "+f"(c[3])
        : "r"(a[0]), "r"(a[1]), "r"(a[2]), "r"(a[3]), "r"(b0), "r"(b1));
}

__device__ __forceinline__ void mma_f16(float* c, const uint32_t* a, uint32_t b0, uint32_t b1) {
    asm volatile(
        "mma.sync.aligned.m16n8k16.row.col.f32.f16.f16.f32 "
        "{%0,%1,%2,%3}, {%4,%5,%6,%7}, {%8,%9}, {%0,%1,%2,%3};\n"
        : "+f"(c[0]), "+f"(c[1]), "+f"(c[2]), "+f"(c[3])
        : "r"(a[0]), "r"(a[1]), "r"(a[2]), "r"(a[3]), "r"(b0), "r"(b1));
}

__device__ __forceinline__ void ldsm4(uint32_t* r, uint32_t a) {
    asm volatile("ldmatrix.sync.aligned.m8n8.x4.shared.b16 {%0,%1,%2,%3}, [%4];"
                 : "=r"(r[0]), "=r"(r[1]), "=r"(r[2]), "=r"(r[3]) : "r"(a));
}

__device__ __forceinline__ void ldsm4t(uint32_t* r, uint32_t a) {
    asm volatile("ldmatrix.sync.aligned.m8n8.x4.trans.shared.b16 {%0,%1,%2,%3}, [%4];"
                 : "=r"(r[0]), "=r"(r[1]), "=r"(r[2]), "=r"(r[3]) : "r"(a));
}

__device__ __forceinline__ void ldgsts16(uint32_t saddr, const void* gp) {
    asm volatile("cp.async.cg.shared.global [%0], [%1], 16;\n" :: "r"(saddr), "l"(gp));
}

__device__ __forceinline__ float ex2(float x) {
    float y;
    asm("ex2.approx.f32 %0, %1;" : "=f"(y) : "f"(x));
    return y;
}

// ---------------------------------------------------------------------------
// Kernel 1: DynamicPosBias MLP -> g_ptab[225][8]
// ---------------------------------------------------------------------------
__device__ __forceinline__ void lnrelu16(const float* p, float* t,
                                         const float* gm, const float* bt) {
    float m = 0.f;
#pragma unroll
    for (int j = 0; j < 16; j++) m += p[j];
    m *= (1.f / 16.f);
    float v = 0.f;
#pragma unroll
    for (int j = 0; j < 16; j++) { float d = p[j] - m; v += d * d; }
    v *= (1.f / 16.f);
    float is = rsqrtf(v + 1e-5f);
#pragma unroll
    for (int j = 0; j < 16; j++) {
        float u = (p[j] - m) * is * gm[j] + bt[j];
        t[j] = u > 0.f ? u : 0.f;
    }
}

__global__ void dpb_kernel(const float* __restrict__ biases,
                           const float* __restrict__ pw, const float* __restrict__ pb,
                           const float* __restrict__ g1, const float* __restrict__ b1,
                           const float* __restrict__ w1, const float* __restrict__ c1,
                           const float* __restrict__ g2, const float* __restrict__ b2,
                           const float* __restrict__ w2, const float* __restrict__ c2,
                           const float* __restrict__ g3, const float* __restrict__ b3,
                           const float* __restrict__ w3, const float* __restrict__ c3) {
    int r = threadIdx.x;
    if (r >= LBIAS) return;
    float p[16], t[16];
    float x0 = biases[2 * r], x1 = biases[2 * r + 1];
#pragma unroll
    for (int j = 0; j < 16; j++) p[j] = x0 * pw[2 * j] + x1 * pw[2 * j + 1] + pb[j];
    lnrelu16(p, t, g1, b1);
#pragma unroll
    for (int o = 0; o < 16; o++) {
        float s = c1[o];
#pragma unroll
        for (int j = 0; j < 16; j++) s += t[j] * w1[o * 16 + j];
        p[o] = s;
    }
    lnrelu16(p, t, g2, b2);
#pragma unroll
    for (int o = 0; o < 16; o++) {
        float s = c2[o];
#pragma unroll
        for (int j = 0; j < 16; j++) s += t[j] * w2[o * 16 + j];
        p[o] = s;
    }
    lnrelu16(p, t, g3, b3);
#pragma unroll
    for (int o = 0; o < 8; o++) {
        float s = c3[o];
#pragma unroll
        for (int j = 0; j < 16; j++) s += t[j] * w3[o * 16 + j];
        g_ptab[r * 8 + o] = s;
    }
}

// ---------------------------------------------------------------------------
// Kernel 1b: presplit. x,qkv_w,proj_w -> single fp16 planes.
// ---------------------------------------------------------------------------
__global__ void presplit_kernel(const float* __restrict__ x,
                                const float* __restrict__ qw,
                                const float* __restrict__ pw) {
    long i = (long)blockIdx.x * 256 + threadIdx.x;  // handles pairs 2i, 2i+1
    uint32_t* dst; const float4* src; long j2;
    if (i < 12845056L) { j2 = 2 * i; src = (const float4*)x; dst = g_xf; }
    else if (i < 12845056L + 49152) { j2 = 2 * (i - 12845056L); src = (const float4*)qw; dst = g_wqf; }
    else if (i < 12845056L + 49152 + 16384) { j2 = 2 * (i - 12845056L - 49152); src = (const float4*)pw; dst = g_wpf; }
    else return;
    float4 f = src[j2 >> 1];
    int m = (int)(j2 >> 7);
    int pc = (int)(j2 & 127);           // even
    int tile = m >> 7, r = m & 127;
    int kb = pc >> 4, q = pc & 15;      // q even -> idx, idx+1 consecutive
    long idx = ((long)(tile * 8 + kb)) * 2048 + plane_pair(r, q);
    *(uint2*)(dst + idx) = make_uint2(pack_f16(f.x, f.y), pack_f16(f.z, f.w));
}

// ---------------------------------------------------------------------------
// Kernel 1c: combined (bias+mask)*log2e table
// ---------------------------------------------------------------------------
__global__ void bmtab_kernel(const float* __restrict__ mask,
                             const int* __restrict__ rel_idx) {
    int wb = blockIdx.x, h = blockIdx.y;
    float* dst = g_bm + (size_t)(wb * 8 + h) * 4096;
    const float* msk = mask + (size_t)wb * 4096;
    for (int i = threadIdx.x; i < 4096; i += blockDim.x)
        dst[i] = (g_ptab[rel_idx[i] * 8 + h] + msk[i]) * LOG2E;
}

// ---------------------------------------------------------------------------
// Kernel 2/4: fp16 single-term GEMM. BM=BN=128, K=256 in 8 chunks of 32.
// 16KB/stage, 3 stages. MODE 0: x @ qkv_w -> scatter q/k/v.
// MODE 1: ctx @ proj_w -> Out.
// ---------------------------------------------------------------------------
template <int MODE>
__global__ __launch_bounds__(256, 2) void gemm_f16(const float* __restrict__ bias,
                                                   float* __restrict__ Out) {
    extern __shared__ char smem[];
    uint32_t sb = (uint32_t)__cvta_generic_to_shared(smem);

    int bm = blockIdx.y, bn = blockIdx.x;
    int tid = threadIdx.x;
    int warp = tid >> 5, lane = tid & 31;
    int wm = warp >> 1, wn = warp & 1;
    int g = lane >> 2, tg = lane & 3;

    const uint32_t* Asrc = MODE ? g_otf : g_xf;
    const uint32_t* Bsrc = MODE ? g_wpf : g_wqf;

    float acc[2][8][4];
#pragma unroll
    for (int a = 0; a < 2; a++)
#pragma unroll
        for (int b = 0; b < 8; b++)
#pragma unroll
            for (int c = 0; c < 4; c++) acc[a][b][c] = 0.f;

    auto mkbase = [&](int r, int lb) {
        int j = r >> 1, a = (r & 1) << 2;
        return (uint32_t)(j * 128 + (((a ^ lb) ^ (j & 7)) << 4));
    };
    int rA = lane & 15, lbA = lane >> 4;
    uint32_t baseA0 = mkbase(wm * 32 + rA, lbA);
    uint32_t baseA1 = mkbase(wm * 32 + 16 + rA, lbA);
    int rB = (lane & 7) | ((lane >> 1) & 8);
    int lbB = (lane >> 3) & 1;
    uint32_t baseB[4];
#pragma unroll
    for (int i = 0; i < 4; i++) baseB[i] = mkbase(wn * 64 + i * 16 + rB, lbB);

    auto issue = [&](int kb, int s) {
        uint32_t S = sb + (uint32_t)s * 16384;
        const uint32_t* srcA = Asrc + (size_t)(bm * 8 + kb) * 2048;
        const uint32_t* srcB = Bsrc + (size_t)(bn * 8 + kb) * 2048;
#pragma unroll
        for (int e = 0; e < 2; e++) {
            int u = tid + e * 256;
            ldgsts16(S + u * 16, srcA + u * 4);
            ldgsts16(S + 8192 + u * 16, srcB + u * 4);
        }
        asm volatile("cp.async.commit_group;\n" ::: "memory");
    };

    issue(0, 0);
    issue(1, 1);

    for (int kb = 0; kb < 8; kb++) {
        int s = kb % 3;
        if (kb < 7) asm volatile("cp.async.wait_group 1;\n" ::: "memory");
        else        asm volatile("cp.async.wait_group 0;\n" ::: "memory");
        __syncthreads();

        uint32_t S = sb + (uint32_t)s * 16384;
#pragma unroll
        for (int ks = 0; ks < 2; ks++) {
            uint32_t uo = ks * 32;
            uint32_t a0[4], a1[4];
            ldsm4(a0, S + (baseA0 ^ uo));
            ldsm4(a1, S + (baseA1 ^ uo));
#pragma unroll
            for (int nfp = 0; nfp < 4; nfp++) {
                int nf0 = 2 * nfp, nf1 = nf0 + 1;
                uint32_t bh[4];
                ldsm4(bh, S + 8192 + (baseB[nfp] ^ uo));
                mma_f16(acc[0][nf0], a0, bh[0], bh[1]);
                mma_f16(acc[1][nf0], a1, bh[0], bh[1]);
                mma_f16(acc[0][nf1], a0, bh[2], bh[3]);
                mma_f16(acc[1][nf1], a1, bh[2], bh[3]);
            }
        }
        if (kb < 6) issue(kb + 2, (kb + 2) % 3);
    }

    int obase = bn * 128 + wn * 64;
#pragma unroll
    for (int nf = 0; nf < 8; nf++) {
        int o = obase + nf * 8 + 2 * tg;
        float bb0 = bias[o], bb1 = bias[o + 1];
#pragma unroll
        for (int mf = 0; mf < 2; mf++) {
#pragma unroll
            for (int r2 = 0; r2 < 2; r2++) {
                int m = bm * 128 + wm * 32 + mf * 16 + g + r2 * 8;
                float v0 = acc[mf][nf][r2 * 2] + bb0;
                float v1 = acc[mf][nf][r2 * 2 + 1] + bb1;
                if (MODE == 1) {
                    *(float2*)(Out + (size_t)m * 256 + o) = make_float2(v0, v1);
                } else {
                    int s = o >> 8, hh = (o >> 5) & 7, d = o & 31;
                    int bw = m >> 6, n = m & 63;
                    size_t di = ((size_t)(bw * 8 + hh) * 64 + n) * 16 + (d >> 1);
                    uint32_t hi, lo;
                    if (s == 0)      { g_q1[di] = pack_hi(v0 * ATT_SCALE_L2E, v1 * ATT_SCALE_L2E); }
                    else if (s == 1) { g_k1[di] = pack_hi(v0, v1); }
                    else             { split2(v0, v1, hi, lo); g_vh[di] = hi; g_vl[di] = lo; }
                }
            }
        }
    }
}

// ---------------------------------------------------------------------------
// Kernel 3: attention. q/k hi-only bf16 QK^T; P.V bf16x3; deferred norm;
// ctx -> single fp16 plane.
// ---------------------------------------------------------------------------
__global__ __launch_bounds__(128, 6) void attn_kernel() {
    __shared__ uint32_t k1s[64][20];
    __shared__ uint32_t vhs[64][20];
    __shared__ uint32_t vls[64][20];
    __shared__ float    bms[64][68];

    int b = blockIdx.x, h = blockIdx.y;
    int tid = threadIdx.x;
    int warp = tid >> 5, lane = tid & 31;
    int g = lane >> 2, tg = lane & 3;
    int mr = warp * 16;

    const uint32_t* qg = g_q1 + (size_t)(b * 8 + h) * 1024;
    const uint32_t* kg = g_k1 + (size_t)(b * 8 + h) * 1024;
    const uint32_t* vhg = g_vh + (size_t)(b * 8 + h) * 1024;
    const uint32_t* vlg = g_vl + (size_t)(b * 8 + h) * 1024;
    const float*    bmr = g_bm + (size_t)((b % NW) * 8 + h) * 4096;

    uint32_t k1b = (uint32_t)__cvta_generic_to_shared(&k1s[0][0]);
#pragma unroll
    for (int e = 0; e < 2; e++) {
        int u = tid + e * 128;
        int t = u >> 2, part = u & 3;
        ldgsts16(k1b + (uint32_t)(t * 80 + part * 16), kg + t * 16 + part * 4);
    }
    asm volatile("cp.async.commit_group;\n" ::: "memory");

    uint32_t vhb = (uint32_t)__cvta_generic_to_shared(&vhs[0][0]);
    uint32_t vlb = (uint32_t)__cvta_generic_to_shared(&vls[0][0]);
#pragma unroll
    for (int e = 0; e < 2; e++) {
        int u = tid + e * 128;
        int t = u >> 2, part = u & 3;
        ldgsts16(vhb + (uint32_t)(t * 80 + part * 16), vhg + t * 16 + part * 4);
        ldgsts16(vlb + (uint32_t)(t * 80 + part * 16), vlg + t * 16 + part * 4);
    }
    asm volatile("cp.async.commit_group;\n" ::: "memory");

    uint32_t bmsb = (uint32_t)__cvta_generic_to_shared(&bms[0][0]);
#pragma unroll
    for (int e = 0; e < 8; e++) {
        int i = lane + 32 * e;
        int rr = warp * 16 + (i >> 4);
        int cu = (i & 15) * 4;
        ldgsts16(bmsb + (uint32_t)(rr * 68 + cu) * 4, bmr + rr * 64 + cu);
    }
    asm volatile("cp.async.commit_group;\n" ::: "memory");

    uint32_t qh_[2][4];
#pragma unroll
    for (int ks = 0; ks < 2; ks++) {
        int j0 = ks * 8;
        qh_[ks][0] = qg[(mr + g) * 16 + j0 + tg];
        qh_[ks][1] = qg[(mr + g + 8) * 16 + j0 + tg];
        qh_[ks][2] = qg[(mr + g) * 16 + j0 + tg + 4];
        qh_[ks][3] = qg[(mr + g + 8) * 16 + j0 + tg + 4];
    }

    asm volatile("cp.async.wait_group 2;\n" ::: "memory");
    __syncthreads();

    float acc[8][4];
#pragma unroll
    for (int a = 0; a < 8; a++)
#pragma unroll
        for (int c = 0; c < 4; c++) acc[a][c] = 0.f;

#pragma unroll
    for (int ks = 0; ks < 2; ks++) {
        int j0 = ks * 8;
#pragma unroll
        for (int nfp = 0; nfp < 4; nfp++) {
            int nf0 = 2 * nfp, nf1 = nf0 + 1;
            int n0 = nf0 * 8 + g;
            uint32_t c0 = k1s[n0][j0 + tg],     c1 = k1s[n0][j0 + tg + 4];
            uint32_t d0 = k1s[n0 + 8][j0 + tg], d1 = k1s[n0 + 8][j0 + tg + 4];
            mma_bf16(acc[nf0], qh_[ks], c0, c1);
            mma_bf16(acc[nf1], qh_[ks], d0, d1);
        }
    }

    asm volatile("cp.async.wait_group 0;\n" ::: "memory");
    __syncthreads();

    int r0 = mr + g, r1 = r0 + 8;
#pragma unroll
    for (int nf = 0; nf < 8; nf++) {
        int n0 = nf * 8 + 2 * tg;
        float2 e0 = *(const float2*)(&bms[r0][n0]);
        float2 e1 = *(const float2*)(&bms[r1][n0]);
        acc[nf][0] += e0.x; acc[nf][1] += e0.y;
        acc[nf][2] += e1.x; acc[nf][3] += e1.y;
    }

    float m0 = -1e30f, m1 = -1e30f;
#pragma unroll
    for (int nf = 0; nf < 8; nf++) {
        m0 = fmaxf(m0, fmaxf(acc[nf][0], acc[nf][1]));
        m1 = fmaxf(m1, fmaxf(acc[nf][2], acc[nf][3]));
    }
    m0 = fmaxf(m0, __shfl_xor_sync(0xffffffffu, m0, 1));
    m0 = fmaxf(m0, __shfl_xor_sync(0xffffffffu, m0, 2));
    m1 = fmaxf(m1, __shfl_xor_sync(0xffffffffu, m1, 1));
    m1 = fmaxf(m1, __shfl_xor_sync(0xffffffffu, m1, 2));

    float s0 = 0.f, s1 = 0.f;
#pragma unroll
    for (int nf = 0; nf < 8; nf++) {
        acc[nf][0] = ex2(acc[nf][0] - m0); s0 += acc[nf][0];
        acc[nf][1] = ex2(acc[nf][1] - m0); s0 += acc[nf][1];
        acc[nf][2] = ex2(acc[nf][2] - m1); s1 += acc[nf][2];
        acc[nf][3] = ex2(acc[nf][3] - m1); s1 += acc[nf][3];
    }

    float oacc[4][4];
#pragma unroll
    for (int a = 0; a < 4; a++)
#pragma unroll
        for (int c = 0; c < 4; c++) oacc[a][c] = 0.f;

    uint32_t vrow = (uint32_t)(((lane >> 3) & 1) * 8 + (lane & 7));
    uint32_t vcol = (uint32_t)((lane >> 4) * 16);
    uint32_t vh_l = vhb + vrow * 80 + vcol;
    uint32_t vl_l = vlb + vrow * 80 + vcol;

#pragma unroll
    for (int ks = 0; ks < 4; ks++) {
        uint32_t ah[4], al[4];
        split2(acc[2 * ks][0],     acc[2 * ks][1],     ah[0], al[0]);
        split2(acc[2 * ks][2],     acc[2 * ks][3],     ah[1], al[1]);
        split2(acc[2 * ks + 1][0], acc[2 * ks + 1][1], ah[2], al[2]);
        split2(acc[2 * ks + 1][2], acc[2 * ks + 1][3], ah[3], al[3]);
        uint32_t ko = (uint32_t)(ks * 16 * 80);
        uint32_t bh0[4], bh1[4], bl0[4], bl1[4];
        ldsm4t(bh0, vh_l + ko);
        ldsm4t(bh1, vh_l + ko + 32);
        ldsm4t(bl0, vl_l + ko);
        ldsm4t(bl1, vl_l + ko + 32);
        mma_bf16(oacc[0], ah, bh0[0], bh0[1]);
        mma_bf16(oacc[1], ah, bh0[2], bh0[3]);
        mma_bf16(oacc[2], ah, bh1[0], bh1[1]);
        mma_bf16(oacc[3], ah, bh1[2], bh1[3]);
        mma_bf16(oacc[0], ah, bl0[0], bl0[1]);
        mma_bf16(oacc[1], ah, bl0[2], bl0[3]);
        mma_bf16(oacc[2], ah, bl1[0], bl1[1]);
        mma_bf16(oacc[3], ah, bl1[2], bl1[3]);
        mma_bf16(oacc[0], al, bh0[0], bh0[1]);
        mma_bf16(oacc[1], al, bh0[2], bh0[3]);
        mma_bf16(oacc[2], al, bh1[0], bh1[1]);
        mma_bf16(oacc[3], al, bh1[2], bh1[3]);
    }

    s0 += __shfl_xor_sync(0xffffffffu, s0, 1);
    s0 += __shfl_xor_sync(0xffffffffu, s0, 2);
    s1 += __shfl_xor_sync(0xffffffffu, s1, 1);
    s1 += __shfl_xor_sync(0xffffffffu, s1, 2);
    float i0 = 1.f / s0, i1 = 1.f / s1;

    // ctx -> single fp16 plane
    int m0r = b * 64 + r0, m1r = b * 64 + r1;
#pragma unroll
    for (int nf = 0; nf < 4; nf++) {
        int dp = h * 16 + nf * 4 + tg;
        int kb = dp >> 4, q = dp & 15;
        {
            size_t idx = ((size_t)((m0r >> 7) * 8 + kb)) * 2048 + plane_pair(m0r & 127, q);
            g_otf[idx] = pack_f16(oacc[nf][0] * i0, oacc[nf][1] * i0);
        }
        {
            size_t idx = ((size_t)((m1r >> 7) * 8 + kb)) * 2048 + plane_pair(m1r & 127, q);
            g_otf[idx] = pack_f16(oacc[nf][2] * i1, oacc[nf][3] * i1);
        }
    }
}

// ---------------------------------------------------------------------------
extern "C" void kernel_launch(void* const* d_in, const int* in_sizes, int n_in,
                              void* d_out, int out_size) {
    (void)in_sizes; (void)n_in; (void)out_size;
    const float* x       = (const float*)d_in[0];
    const float* mask    = (const float*)d_in[1];
    const float* qkv_w   = (const float*)d_in[2];
    const float* qkv_b   = (const float*)d_in[3];
    const float* proj_w  = (const float*)d_in[4];
    const float* proj_b  = (const float*)d_in[5];
    const float* pposw   = (const float*)d_in[6];
    const float* pposb   = (const float*)d_in[7];
    const float* ln1g    = (const float*)d_in[8];
    const float* ln1b    = (const float*)d_in[9];
    const float* fc1w    = (const float*)d_in[10];
    const float* fc1b    = (const float*)d_in[11];
    const float* ln2g    = (const float*)d_in[12];
    const float* ln2b    = (const float*)d_in[13];
    const float* fc2w    = (const float*)d_in[14];
    const float* fc2b    = (const float*)d_in[15];
    const float* ln3g    = (const float*)d_in[16];
    const float* ln3b    = (const float*)d_in[17];
    const float* fc3w    = (const float*)d_in[18];
    const float* fc3b    = (const float*)d_in[19];
    const float* biases  = (const float*)d_in[20];
    const int*   rel_idx = (const int*)d_in[21];
    float* out = (float*)d_out;

    static bool attr_set = false;
    if (!attr_set) {
        cudaFuncSetAttribute(gemm_f16<0>, cudaFuncAttributeMaxDynamicSharedMemorySize, 49152);
        cudaFuncSetAttribute(gemm_f16<1>, cudaFuncAttributeMaxDynamicSharedMemorySize, 49152);
        attr_set = true;
    }

    dpb_kernel<<<1, 256>>>(biases, pposw, pposb, ln1g, ln1b, fc1w, fc1b,
                           ln2g, ln2b, fc2w, fc2b, ln3g, ln3b, fc3w, fc3b);
    presplit_kernel<<<50432, 256>>>(x, qkv_w, proj_w);
    bmtab_kernel<<<dim3(NW, HEADS), 256>>>(mask, rel_idx);
    gemm_f16<0><<<dim3(6, 1568), 256, 49152>>>(qkv_b, nullptr);
    attn_kernel<<<dim3(B_WIN, HEADS), 128>>>();
    gemm_f16<1><<<dim3(2, 1568), 256, 49152>>>(proj_b, out);
}